// round 2
// baseline (speedup 1.0000x reference)
#include <cuda_runtime.h>
#include <cstdint>
#include <cstddef>

#define LSEQ 2048
#define DMODEL 1024
#define DI 2048       // D_INNER
#define DSTATE 16
#define DTRANK 64
#define HIDF 4096
#define NPROJ 96      // DT_RANK + 2*D_STATE

// ---------------- scratch (device globals; no allocation allowed) ----------------
__device__ float g_hln[LSEQ * DMODEL];
__device__ float g_xz[LSEQ * 2 * DI];
__device__ float g_xc[LSEQ * DI];
__device__ float g_proj[LSEQ * NPROJ];
__device__ float g_delta[LSEQ * DI];
__device__ float g_ys[LSEQ * DI];
__device__ float g_y[LSEQ * DI];
__device__ float g_h[LSEQ * DMODEL];
__device__ float g_n[LSEQ * DMODEL];
__device__ float g_f1[LSEQ * HIDF];

// ---------------- LayerNorm: one block per row, 256 threads, D=1024 ----------------
__global__ void ln_kernel(const float* __restrict__ x, const float* __restrict__ g,
                          const float* __restrict__ b, float* __restrict__ out) {
    __shared__ float rs[8], rq[8];
    const int tid = threadIdx.x;
    const size_t base = (size_t)blockIdx.x * DMODEL;
    float4 xv = *(const float4*)(x + base + tid * 4);
    float s = xv.x + xv.y + xv.z + xv.w;
    float q = xv.x * xv.x + xv.y * xv.y + xv.z * xv.z + xv.w * xv.w;
#pragma unroll
    for (int o = 16; o > 0; o >>= 1) {
        s += __shfl_xor_sync(0xffffffffu, s, o);
        q += __shfl_xor_sync(0xffffffffu, q, o);
    }
    if ((tid & 31) == 0) { rs[tid >> 5] = s; rq[tid >> 5] = q; }
    __syncthreads();
    s = rs[0] + rs[1] + rs[2] + rs[3] + rs[4] + rs[5] + rs[6] + rs[7];
    q = rq[0] + rq[1] + rq[2] + rq[3] + rq[4] + rq[5] + rq[6] + rq[7];
    const float mu = s * (1.0f / DMODEL);
    const float var = q * (1.0f / DMODEL) - mu * mu;
    const float rstd = rsqrtf(var + 1e-5f);
    float4 gv = *(const float4*)(g + tid * 4);
    float4 bv = *(const float4*)(b + tid * 4);
    float4 o4;
    o4.x = (xv.x - mu) * rstd * gv.x + bv.x;
    o4.y = (xv.y - mu) * rstd * gv.y + bv.y;
    o4.z = (xv.z - mu) * rstd * gv.z + bv.z;
    o4.w = (xv.w - mu) * rstd * gv.w + bv.w;
    *(float4*)(out + base + tid * 4) = o4;
}

// ---------------- Generic SGEMM:  C[M,N] = A[M,K] @ W[N,K]^T  (+ epilogue) ----------------
// Modes: 0 = store, 1 = bias+softplus, 2 = bias+relu, 3 = +res1, 4 = bias+res1+res2
#define BM 128
#define BN 128
#define BKK 8
#define TM 8
#define TN 8

__global__ __launch_bounds__(256, 2)
void sgemm_kernel(const float* __restrict__ A, int lda,
                  const float* __restrict__ W,
                  float* __restrict__ C, int ldc,
                  int M, int N, int K, int mode,
                  const float* __restrict__ bias,
                  const float* __restrict__ res1, int ldr1,
                  const float* __restrict__ res2, int ldr2) {
    __shared__ float As[BKK][BM];
    __shared__ float Bs[BKK][BN];

    const int tid = threadIdx.x;
    const int bm = blockIdx.y * BM;
    const int bn = blockIdx.x * BN;

    const int aRow = tid >> 1;          // 0..127
    const int aCol = (tid & 1) * 4;     // 0 or 4
    const int bRow = tid >> 1;          // n index 0..127
    const int bCol = (tid & 1) * 4;     // k index 0 or 4

    const int tx = tid & 15;
    const int ty = tid >> 4;

    float acc[TM][TN];
#pragma unroll
    for (int i = 0; i < TM; ++i)
#pragma unroll
        for (int j = 0; j < TN; ++j) acc[i][j] = 0.0f;

    const bool bOk = (bn + bRow) < N;

    for (int k0 = 0; k0 < K; k0 += BKK) {
        float4 av = *(const float4*)(A + (size_t)(bm + aRow) * lda + k0 + aCol);
        float4 bv = make_float4(0.f, 0.f, 0.f, 0.f);
        if (bOk) bv = *(const float4*)(W + (size_t)(bn + bRow) * K + k0 + bCol);
        __syncthreads();
        As[aCol + 0][aRow] = av.x;
        As[aCol + 1][aRow] = av.y;
        As[aCol + 2][aRow] = av.z;
        As[aCol + 3][aRow] = av.w;
        Bs[bCol + 0][bRow] = bv.x;
        Bs[bCol + 1][bRow] = bv.y;
        Bs[bCol + 2][bRow] = bv.z;
        Bs[bCol + 3][bRow] = bv.w;
        __syncthreads();
#pragma unroll
        for (int kk = 0; kk < BKK; ++kk) {
            float rm[TM], rn[TN];
            *(float4*)&rm[0] = *(const float4*)&As[kk][ty * TM];
            *(float4*)&rm[4] = *(const float4*)&As[kk][ty * TM + 4];
            *(float4*)&rn[0] = *(const float4*)&Bs[kk][tx * TN];
            *(float4*)&rn[4] = *(const float4*)&Bs[kk][tx * TN + 4];
#pragma unroll
            for (int i = 0; i < TM; ++i)
#pragma unroll
                for (int j = 0; j < TN; ++j) acc[i][j] = fmaf(rm[i], rn[j], acc[i][j]);
        }
    }

#pragma unroll
    for (int i = 0; i < TM; ++i) {
        const int row = bm + ty * TM + i;
#pragma unroll
        for (int j = 0; j < TN; ++j) {
            const int col = bn + tx * TN + j;
            if (col < N) {
                float v = acc[i][j];
                if (mode == 1) {
                    v += bias[col];
                    v = fmaxf(v, 0.0f) + log1pf(__expf(-fabsf(v)));   // softplus
                } else if (mode == 2) {
                    v = fmaxf(v + bias[col], 0.0f);                    // relu
                } else if (mode == 3) {
                    v += res1[(size_t)row * ldr1 + col];
                } else if (mode == 4) {
                    v += bias[col] + res1[(size_t)row * ldr1 + col] + res2[(size_t)row * ldr2 + col];
                }
                C[(size_t)row * ldc + col] = v;
            }
        }
    }
}

// ---------------- causal depthwise conv (D_CONV=4) + SiLU ----------------
__global__ void conv_silu_kernel(const float* __restrict__ conv_w, const float* __restrict__ conv_b) {
    const int idx = blockIdx.x * blockDim.x + threadIdx.x;   // over L*DI
    const int d = idx & (DI - 1);
    const int t = idx >> 11;
    float acc = conv_b[d];
#pragma unroll
    for (int k = 0; k < 4; ++k) {
        const int tt = t + k - 3;
        if (tt >= 0) acc = fmaf(g_xz[(size_t)tt * (2 * DI) + d], conv_w[d * 4 + k], acc);
    }
    const float sg = 1.0f / (1.0f + __expf(-acc));
    g_xc[idx] = acc * sg;
}

// ---------------- selective scan: one state per lane, 16 lanes per channel ----------------
// block = 256 threads = 16 channels; grid = DI/16 = 128 blocks
__global__ void scan_kernel(const float* __restrict__ A_log) {
    const int s = threadIdx.x & 15;
    const int d = blockIdx.x * 16 + (threadIdx.x >> 4);
    const float a = -__expf(A_log[d * DSTATE + s]);   // A[d,s] (negative)

    float h = 0.0f;
    constexpr int PF = 8;
    float pd[PF], px[PF], pb[PF], pc[PF];
#pragma unroll
    for (int i = 0; i < PF; ++i) {
        pd[i] = g_delta[(size_t)i * DI + d];
        px[i] = g_xc[(size_t)i * DI + d];
        pb[i] = g_proj[i * NPROJ + DTRANK + s];
        pc[i] = g_proj[i * NPROJ + DTRANK + DSTATE + s];
    }

#pragma unroll 8
    for (int t = 0; t < LSEQ; ++t) {
        const int sl = t & (PF - 1);
        const float dt_ = pd[sl];
        const float xc_ = px[sl];
        const float b_ = pb[sl];
        const float c_ = pc[sl];
        const int tp = t + PF;
        if (tp < LSEQ) {
            pd[sl] = g_delta[(size_t)tp * DI + d];
            px[sl] = g_xc[(size_t)tp * DI + d];
            pb[sl] = g_proj[tp * NPROJ + DTRANK + s];
            pc[sl] = g_proj[tp * NPROJ + DTRANK + DSTATE + s];
        }
        const float dA = __expf(a * dt_);
        h = fmaf(h, dA, dt_ * xc_ * b_);
        float p = h * c_;
        p += __shfl_xor_sync(0xffffffffu, p, 1);
        p += __shfl_xor_sync(0xffffffffu, p, 2);
        p += __shfl_xor_sync(0xffffffffu, p, 4);
        p += __shfl_xor_sync(0xffffffffu, p, 8);
        if (s == 0) g_ys[(size_t)t * DI + d] = p;
    }
}

// ---------------- y = (ys + xc*Dp) * silu(z) ----------------
__global__ void ygate_kernel(const float* __restrict__ Dp) {
    const int idx = blockIdx.x * blockDim.x + threadIdx.x;
    const int d = idx & (DI - 1);
    const int t = idx >> 11;
    const float z = g_xz[(size_t)t * (2 * DI) + DI + d];
    const float sig = 1.0f / (1.0f + __expf(-z));
    g_y[idx] = fmaf(g_xc[idx], Dp[d], g_ys[idx]) * (z * sig);
}

// ---------------- launch ----------------
extern "C" void kernel_launch(void* const* d_in, const int* in_sizes, int n_in,
                              void* d_out, int out_size) {
    const float* x         = (const float*)d_in[0];
    const float* ln1_g     = (const float*)d_in[1];
    const float* ln1_b     = (const float*)d_in[2];
    const float* ln2_g     = (const float*)d_in[3];
    const float* ln2_b     = (const float*)d_in[4];
    const float* in_proj_w = (const float*)d_in[5];
    const float* conv_w    = (const float*)d_in[6];
    const float* conv_b    = (const float*)d_in[7];
    const float* x_proj_w  = (const float*)d_in[8];
    const float* dt_proj_w = (const float*)d_in[9];
    const float* dt_proj_b = (const float*)d_in[10];
    const float* A_log     = (const float*)d_in[11];
    const float* D_param   = (const float*)d_in[12];
    const float* out_proj_w= (const float*)d_in[13];
    const float* ffn_w1    = (const float*)d_in[14];
    const float* ffn_b1    = (const float*)d_in[15];
    const float* ffn_w2    = (const float*)d_in[16];
    const float* ffn_b2    = (const float*)d_in[17];
    float* out = (float*)d_out;

    float *hln, *xz, *xc, *proj, *delta, *ys, *y, *hbuf, *nbuf, *f1;
    cudaGetSymbolAddress((void**)&hln,   g_hln);
    cudaGetSymbolAddress((void**)&xz,    g_xz);
    cudaGetSymbolAddress((void**)&xc,    g_xc);
    cudaGetSymbolAddress((void**)&proj,  g_proj);
    cudaGetSymbolAddress((void**)&delta, g_delta);
    cudaGetSymbolAddress((void**)&ys,    g_ys);
    cudaGetSymbolAddress((void**)&y,     g_y);
    cudaGetSymbolAddress((void**)&hbuf,  g_h);
    cudaGetSymbolAddress((void**)&nbuf,  g_n);
    cudaGetSymbolAddress((void**)&f1,    g_f1);

    // 1) h_ln = LN1(x)
    ln_kernel<<<LSEQ, 256>>>(x, ln1_g, ln1_b, hln);

    // 2) xz = h_ln @ in_proj_w^T   [2048, 4096]
    sgemm_kernel<<<dim3((2 * DI) / BN, LSEQ / BM), 256>>>(
        hln, DMODEL, in_proj_w, xz, 2 * DI, LSEQ, 2 * DI, DMODEL, 0,
        nullptr, nullptr, 0, nullptr, 0);

    // 3) xc = silu(conv(xm) + b)
    conv_silu_kernel<<<(LSEQ * DI) / 256, 256>>>(conv_w, conv_b);

    // 4) proj = xc @ x_proj_w^T   [2048, 96]
    sgemm_kernel<<<dim3(1, LSEQ / BM), 256>>>(
        xc, DI, x_proj_w, proj, NPROJ, LSEQ, NPROJ, DI, 0,
        nullptr, nullptr, 0, nullptr, 0);

    // 5) delta = softplus(dt @ dt_proj_w^T + dt_b)   [2048, 2048]
    sgemm_kernel<<<dim3(DI / BN, LSEQ / BM), 256>>>(
        proj, NPROJ, dt_proj_w, delta, DI, LSEQ, DI, DTRANK, 1,
        dt_proj_b, nullptr, 0, nullptr, 0);

    // 6) selective scan -> ys
    scan_kernel<<<DI / 16, 256>>>(A_log);

    // 7) y = (ys + xc*Dp) * silu(z)
    ygate_kernel<<<(LSEQ * DI) / 256, 256>>>(D_param);

    // 8) h = y @ out_proj_w^T + x   [2048, 1024]
    sgemm_kernel<<<dim3(DMODEL / BN, LSEQ / BM), 256>>>(
        y, DI, out_proj_w, hbuf, DMODEL, LSEQ, DMODEL, DI, 3,
        nullptr, x, DMODEL, nullptr, 0);

    // 9) n = LN2(h)
    ln_kernel<<<LSEQ, 256>>>(hbuf, ln2_g, ln2_b, nbuf);

    // 10) f1 = relu(n @ ffn_w1^T + b1)   [2048, 4096]
    sgemm_kernel<<<dim3(HIDF / BN, LSEQ / BM), 256>>>(
        nbuf, DMODEL, ffn_w1, f1, HIDF, LSEQ, HIDF, DMODEL, 2,
        ffn_b1, nullptr, 0, nullptr, 0);

    // 11) out = f1 @ ffn_w2^T + b2 + n + h   [2048, 1024]
    sgemm_kernel<<<dim3(DMODEL / BN, LSEQ / BM), 256>>>(
        f1, HIDF, ffn_w2, out, DMODEL, LSEQ, DMODEL, HIDF, 4,
        ffn_b2, nbuf, DMODEL, hbuf, DMODEL);
}

// round 4
// speedup vs baseline: 1.7339x; 1.7339x over previous
#include <cuda_runtime.h>
#include <cuda_bf16.h>
#include <cstdint>
#include <cstddef>

#define LSEQ 2048
#define DMODEL 1024
#define DI 2048
#define DSTATE 16
#define DTRANK 64
#define HIDF 4096
#define NPROJ 96

typedef __nv_bfloat16 bf16;

// ------------------------------------------------------------------
// scratch (device globals; no allocation allowed)
// ------------------------------------------------------------------
__device__ float  g_xz[LSEQ * 2 * DI];
__device__ float  g_xc[LSEQ * DI];
__device__ float  g_proj[LSEQ * NPROJ];
__device__ float2 g_dx[LSEQ * DI];          // (delta, delta*xc)
__device__ float2 g_bc[LSEQ * DSTATE];      // (B, C)
__device__ float  g_ys[LSEQ * DI];
__device__ float  g_h[LSEQ * DMODEL];
__device__ float  g_n[LSEQ * DMODEL];

__device__ bf16 g_hln_h[LSEQ * DMODEL], g_hln_l[LSEQ * DMODEL];
__device__ bf16 g_xc_h[LSEQ * DI],      g_xc_l[LSEQ * DI];
__device__ bf16 g_y_h[LSEQ * DI],       g_y_l[LSEQ * DI];
__device__ bf16 g_n_h[LSEQ * DMODEL],   g_n_l[LSEQ * DMODEL];
__device__ bf16 g_f1_h[LSEQ * HIDF],    g_f1_l[LSEQ * HIDF];

__device__ bf16 g_win_h[2 * DI * DMODEL], g_win_l[2 * DI * DMODEL];
__device__ bf16 g_wxp_h[NPROJ * DI],      g_wxp_l[NPROJ * DI];
__device__ bf16 g_wout_h[DMODEL * DI],    g_wout_l[DMODEL * DI];
__device__ bf16 g_wf1_h[HIDF * DMODEL],   g_wf1_l[HIDF * DMODEL];
__device__ bf16 g_wf2_h[DMODEL * HIDF],   g_wf2_l[DMODEL * HIDF];

// ------------------------------------------------------------------
// PTX helpers (sm_80-level only: cp.async, ldmatrix, mma.sync)
// ------------------------------------------------------------------
__device__ __forceinline__ uint32_t smem_u32(const void* p) {
    uint32_t a;
    asm("{ .reg .u64 t; cvta.to.shared.u64 t, %1; cvt.u32.u64 %0, t; }" : "=r"(a) : "l"(p));
    return a;
}
__device__ __forceinline__ void cp16(uint32_t dst, const void* src, bool p) {
    int sz = p ? 16 : 0;
    asm volatile("cp.async.cg.shared.global [%0], [%1], 16, %2;"
                 :: "r"(dst), "l"(src), "r"(sz) : "memory");
}
__device__ __forceinline__ void cp_commit() {
    asm volatile("cp.async.commit_group;" ::: "memory");
}
__device__ __forceinline__ void cp_wait1() {
    asm volatile("cp.async.wait_group 1;" ::: "memory");
}
__device__ __forceinline__ void ldsm_x4(uint32_t addr, uint32_t* r) {
    asm volatile("ldmatrix.sync.aligned.m8n8.x4.shared.b16 {%0,%1,%2,%3}, [%4];"
                 : "=r"(r[0]), "=r"(r[1]), "=r"(r[2]), "=r"(r[3]) : "r"(addr));
}
__device__ __forceinline__ void mma_bf16(float* c, const uint32_t* a, const uint32_t* b) {
    asm volatile(
        "mma.sync.aligned.m16n8k16.row.col.f32.bf16.bf16.f32 "
        "{%0,%1,%2,%3}, {%4,%5,%6,%7}, {%8,%9}, {%0,%1,%2,%3};"
        : "+f"(c[0]), "+f"(c[1]), "+f"(c[2]), "+f"(c[3])
        : "r"(a[0]), "r"(a[1]), "r"(a[2]), "r"(a[3]), "r"(b[0]), "r"(b[1]));
}
__device__ __forceinline__ uint32_t sw64(uint32_t bo) { return bo ^ ((bo >> 3) & 0x30); }

// ------------------------------------------------------------------
// mma.sync GEMM: C[M,N] = A[M,K] @ W[N,K]^T, bf16 hi/lo compensated.
// grid = (ceil(N/128), M/128), 256 threads (8 warps, each 32x64).
// modes: 0 store f32 | 1 +res1 f32 | 2 bias+relu -> bf16 hi/lo | 3 bias+res1+res2 f32
// smem: 3 stages x (Ah 8K | Al 8K | Bh 8K | Bl 8K) = 98304 B
// ------------------------------------------------------------------
#define STAGE_BYTES 32768
#define SM_GEMM_TOTAL (3 * STAGE_BYTES)

__device__ __forceinline__ void stage_load(
    uint32_t st, const bf16* __restrict__ Ah, const bf16* __restrict__ Al,
    const bf16* __restrict__ Bh, const bf16* __restrict__ Bl,
    int bm, int bn, int K, int k0, int bvalid, int tid) {
#pragma unroll
    for (int i = 0; i < 2; ++i) {
        const int idx = tid + i * 256;          // 0..511
        const int r = idx >> 2;                 // 0..127
        const int q = idx & 3;                  // 16B quad within 64B row
        const uint32_t sw = sw64(r * 64 + q * 16);
        const size_t goff = (size_t)r * K + k0 + q * 8;
        cp16(st + 0 + sw, Ah + (size_t)bm * K + goff, true);
        cp16(st + 8192 + sw, Al + (size_t)bm * K + goff, true);
        const bool p = r < bvalid;
        cp16(st + 16384 + sw, Bh + (size_t)bn * K + goff, p);
        cp16(st + 24576 + sw, Bl + (size_t)bn * K + goff, p);
    }
}

__global__ __launch_bounds__(256, 1)
void tc_gemm(const bf16* __restrict__ Ah, const bf16* __restrict__ Al,
             const bf16* __restrict__ Bh, const bf16* __restrict__ Bl,
             float* __restrict__ C, bf16* __restrict__ Oh, bf16* __restrict__ Ol,
             int ldc, int N, int K, int mode,
             const float* __restrict__ bias,
             const float* __restrict__ res1, int ldr1,
             const float* __restrict__ res2, int ldr2) {
    extern __shared__ char smem[];
    const uint32_t sb = smem_u32(smem);
    const int tid = threadIdx.x;
    const int wid = tid >> 5, lid = tid & 31;
    const int bm = blockIdx.y * 128;
    const int bn = blockIdx.x * 128;
    const int wm = (wid & 3) * 32;     // warp M offset in tile
    const int wn = (wid >> 2) * 64;    // warp N offset in tile
    const int bvalid = (N - bn) < 128 ? (N - bn) : 128;
    const int nch = K >> 5;            // 32-wide k blocks

    float acc[2][8][4];
#pragma unroll
    for (int mf = 0; mf < 2; ++mf)
#pragma unroll
        for (int nf = 0; nf < 8; ++nf)
#pragma unroll
            for (int v = 0; v < 4; ++v) acc[mf][nf][v] = 0.0f;

    // per-lane ldmatrix address components
    const int mat = lid >> 3;          // which 8x8 matrix this lane addresses
    const int lrow = lid & 7;
    // A: mat0:(m0-7,k0-7) mat1:(m8-15,k0-7) mat2:(m0-7,k8-15) mat3:(m8-15,k8-15)
    const int rowA = wm + (mat & 1) * 8 + lrow;
    const int kqA = (mat >> 1);        // 8-elem k group
    // B: mat0:(n0-7,k0-7) mat1:(n0-7,k8-15) mat2:(n8-15,k0-7) mat3:(n8-15,k8-15)
    const int rowB = wn + (mat >> 1) * 8 + lrow;
    const int kqB = (mat & 1);

    // prologue: stages 0,1
    stage_load(sb + 0 * STAGE_BYTES, Ah, Al, Bh, Bl, bm, bn, K, 0, bvalid, tid);
    cp_commit();
    if (nch > 1)
        stage_load(sb + 1 * STAGE_BYTES, Ah, Al, Bh, Bl, bm, bn, K, 32, bvalid, tid);
    cp_commit();

    for (int c = 0; c < nch; ++c) {
        cp_wait1();
        __syncthreads();
        if (c + 2 < nch)
            stage_load(sb + ((c + 2) % 3) * STAGE_BYTES, Ah, Al, Bh, Bl,
                       bm, bn, K, (c + 2) * 32, bvalid, tid);
        cp_commit();

        const uint32_t base = sb + (c % 3) * STAGE_BYTES;
#pragma unroll
        for (int ks = 0; ks < 2; ++ks) {
            uint32_t ah[2][4], al[2][4], bh[16], bl[16];
#pragma unroll
            for (int mf = 0; mf < 2; ++mf) {
                const uint32_t bo = (uint32_t)(rowA + mf * 16) * 64 + ks * 32 + kqA * 16;
                const uint32_t sw = sw64(bo);
                ldsm_x4(base + 0 + sw, ah[mf]);
                ldsm_x4(base + 8192 + sw, al[mf]);
            }
#pragma unroll
            for (int p = 0; p < 4; ++p) {
                const uint32_t bo = (uint32_t)(rowB + p * 16) * 64 + ks * 32 + kqB * 16;
                const uint32_t sw = sw64(bo);
                ldsm_x4(base + 16384 + sw, &bh[p * 4]);
                ldsm_x4(base + 24576 + sw, &bl[p * 4]);
            }
#pragma unroll
            for (int mf = 0; mf < 2; ++mf)
#pragma unroll
                for (int nf = 0; nf < 8; ++nf) {
                    mma_bf16(acc[mf][nf], ah[mf], &bh[nf * 2]);
                    mma_bf16(acc[mf][nf], ah[mf], &bl[nf * 2]);
                    mma_bf16(acc[mf][nf], al[mf], &bh[nf * 2]);
                }
        }
    }

    // epilogue: c0,c1 -> (row, col..col+1); c2,c3 -> (row+8, ...)
    const int erow0 = bm + wm + (lid >> 2);
    const int ecol0 = bn + wn + (lid & 3) * 2;
#pragma unroll
    for (int mf = 0; mf < 2; ++mf)
#pragma unroll
        for (int nf = 0; nf < 8; ++nf)
#pragma unroll
            for (int half = 0; half < 2; ++half) {
                const int row = erow0 + mf * 16 + half * 8;
                const int col = ecol0 + nf * 8;
                if (col >= N) continue;
                float v0 = acc[mf][nf][half * 2 + 0];
                float v1 = acc[mf][nf][half * 2 + 1];
                if (mode == 0) {
                    *(float2*)(C + (size_t)row * ldc + col) = make_float2(v0, v1);
                } else if (mode == 1) {
                    const float2 rr = *(const float2*)(res1 + (size_t)row * ldr1 + col);
                    *(float2*)(C + (size_t)row * ldc + col) = make_float2(v0 + rr.x, v1 + rr.y);
                } else if (mode == 2) {
                    const float2 bb = *(const float2*)(bias + col);
                    v0 = fmaxf(v0 + bb.x, 0.f);
                    v1 = fmaxf(v1 + bb.y, 0.f);
                    const bf16 h0 = __float2bfloat16(v0), h1 = __float2bfloat16(v1);
                    *(__nv_bfloat162*)(Oh + (size_t)row * ldc + col) = __nv_bfloat162(h0, h1);
                    *(__nv_bfloat162*)(Ol + (size_t)row * ldc + col) =
                        __nv_bfloat162(__float2bfloat16(v0 - __bfloat162float(h0)),
                                       __float2bfloat16(v1 - __bfloat162float(h1)));
                } else {
                    const float2 bb = *(const float2*)(bias + col);
                    const float2 r1 = *(const float2*)(res1 + (size_t)row * ldr1 + col);
                    const float2 r2 = *(const float2*)(res2 + (size_t)row * ldr2 + col);
                    *(float2*)(C + (size_t)row * ldc + col) =
                        make_float2(v0 + bb.x + r1.x + r2.x, v1 + bb.y + r1.y + r2.y);
                }
            }
}

// ------------------------------------------------------------------
// LayerNorm (D=1024): optional fp32 out + bf16 hi/lo out
// ------------------------------------------------------------------
__global__ void ln_kernel(const float* __restrict__ x, const float* __restrict__ g,
                          const float* __restrict__ b, float* __restrict__ outf,
                          bf16* __restrict__ oh, bf16* __restrict__ ol) {
    __shared__ float rs[8], rq[8];
    const int tid = threadIdx.x;
    const size_t base = (size_t)blockIdx.x * DMODEL;
    float4 xv = *(const float4*)(x + base + tid * 4);
    float s = xv.x + xv.y + xv.z + xv.w;
    float q = xv.x * xv.x + xv.y * xv.y + xv.z * xv.z + xv.w * xv.w;
#pragma unroll
    for (int o = 16; o > 0; o >>= 1) {
        s += __shfl_xor_sync(0xffffffffu, s, o);
        q += __shfl_xor_sync(0xffffffffu, q, o);
    }
    if ((tid & 31) == 0) { rs[tid >> 5] = s; rq[tid >> 5] = q; }
    __syncthreads();
    s = rs[0] + rs[1] + rs[2] + rs[3] + rs[4] + rs[5] + rs[6] + rs[7];
    q = rq[0] + rq[1] + rq[2] + rq[3] + rq[4] + rq[5] + rq[6] + rq[7];
    const float mu = s * (1.0f / DMODEL);
    const float var = q * (1.0f / DMODEL) - mu * mu;
    const float rstd = rsqrtf(var + 1e-5f);
    float4 gv = *(const float4*)(g + tid * 4);
    float4 bv = *(const float4*)(b + tid * 4);
    float o0 = (xv.x - mu) * rstd * gv.x + bv.x;
    float o1 = (xv.y - mu) * rstd * gv.y + bv.y;
    float o2 = (xv.z - mu) * rstd * gv.z + bv.z;
    float o3 = (xv.w - mu) * rstd * gv.w + bv.w;
    if (outf) *(float4*)(outf + base + tid * 4) = make_float4(o0, o1, o2, o3);
    bf16 h0 = __float2bfloat16(o0), h1 = __float2bfloat16(o1);
    bf16 h2 = __float2bfloat16(o2), h3 = __float2bfloat16(o3);
    __nv_bfloat162* ph = (__nv_bfloat162*)(oh + base + tid * 4);
    ph[0] = __nv_bfloat162(h0, h1); ph[1] = __nv_bfloat162(h2, h3);
    __nv_bfloat162* pl = (__nv_bfloat162*)(ol + base + tid * 4);
    pl[0] = __nv_bfloat162(__float2bfloat16(o0 - __bfloat162float(h0)),
                           __float2bfloat16(o1 - __bfloat162float(h1)));
    pl[1] = __nv_bfloat162(__float2bfloat16(o2 - __bfloat162float(h2)),
                           __float2bfloat16(o3 - __bfloat162float(h3)));
}

// ------------------------------------------------------------------
// weight fp32 -> bf16 hi/lo
// ------------------------------------------------------------------
__global__ void cvt_hl(const float* __restrict__ src, bf16* __restrict__ h,
                       bf16* __restrict__ l, int n) {
    const int i = blockIdx.x * blockDim.x + threadIdx.x;
    if (i < n) {
        const float x = src[i];
        const bf16 hh = __float2bfloat16(x);
        h[i] = hh;
        l[i] = __float2bfloat16(x - __bfloat162float(hh));
    }
}

// ------------------------------------------------------------------
// causal depthwise conv + SiLU -> xc fp32 + hi/lo
// ------------------------------------------------------------------
__global__ void conv_silu_kernel(const float* __restrict__ conv_w, const float* __restrict__ conv_b) {
    const int idx = blockIdx.x * blockDim.x + threadIdx.x;
    const int d = idx & (DI - 1);
    const int t = idx >> 11;
    float acc = conv_b[d];
#pragma unroll
    for (int k = 0; k < 4; ++k) {
        const int tt = t + k - 3;
        if (tt >= 0) acc = fmaf(g_xz[(size_t)tt * (2 * DI) + d], conv_w[d * 4 + k], acc);
    }
    const float v = acc / (1.0f + __expf(-acc));
    g_xc[idx] = v;
    const bf16 hh = __float2bfloat16(v);
    g_xc_h[idx] = hh;
    g_xc_l[idx] = __float2bfloat16(v - __bfloat162float(hh));
}

// ------------------------------------------------------------------
// pack (B, C) from proj
// ------------------------------------------------------------------
__global__ void pack_bc_kernel() {
    const int i = blockIdx.x * blockDim.x + threadIdx.x;   // L*16
    const int t = i >> 4, s = i & 15;
    g_bc[i] = make_float2(g_proj[t * NPROJ + DTRANK + s],
                          g_proj[t * NPROJ + DTRANK + DSTATE + s]);
}

// ------------------------------------------------------------------
// delta GEMM (SIMT, K=64): dx = (softplus(dt @ Wdt^T + b), delta*xc)
// ------------------------------------------------------------------
__global__ __launch_bounds__(256, 2)
void delta_gemm(const float* __restrict__ P, const float* __restrict__ W,
                const float* __restrict__ bias) {
    __shared__ float As[8][128];
    __shared__ float Bs[8][128];
    const int tid = threadIdx.x;
    const int bm = blockIdx.y * 128;
    const int bn = blockIdx.x * 128;
    const int aRow = tid >> 1, aCol = (tid & 1) * 4;
    const int tx = tid & 15, ty = tid >> 4;
    float acc[8][8];
#pragma unroll
    for (int i = 0; i < 8; ++i)
#pragma unroll
        for (int j = 0; j < 8; ++j) acc[i][j] = 0.0f;
    for (int k0 = 0; k0 < 64; k0 += 8) {
        float4 av = *(const float4*)(P + (size_t)(bm + aRow) * NPROJ + k0 + aCol);
        float4 bv = *(const float4*)(W + (size_t)(bn + aRow) * 64 + k0 + aCol);
        __syncthreads();
        As[aCol + 0][aRow] = av.x; As[aCol + 1][aRow] = av.y;
        As[aCol + 2][aRow] = av.z; As[aCol + 3][aRow] = av.w;
        Bs[aCol + 0][aRow] = bv.x; Bs[aCol + 1][aRow] = bv.y;
        Bs[aCol + 2][aRow] = bv.z; Bs[aCol + 3][aRow] = bv.w;
        __syncthreads();
#pragma unroll
        for (int kk = 0; kk < 8; ++kk) {
            float rm[8], rn[8];
            *(float4*)&rm[0] = *(const float4*)&As[kk][ty * 8];
            *(float4*)&rm[4] = *(const float4*)&As[kk][ty * 8 + 4];
            *(float4*)&rn[0] = *(const float4*)&Bs[kk][tx * 8];
            *(float4*)&rn[4] = *(const float4*)&Bs[kk][tx * 8 + 4];
#pragma unroll
            for (int i = 0; i < 8; ++i)
#pragma unroll
                for (int j = 0; j < 8; ++j) acc[i][j] = fmaf(rm[i], rn[j], acc[i][j]);
        }
    }
#pragma unroll
    for (int i = 0; i < 8; ++i) {
        const int row = bm + ty * 8 + i;
#pragma unroll
        for (int j = 0; j < 8; ++j) {
            const int col = bn + tx * 8 + j;
            float v = acc[i][j] + bias[col];
            v = fmaxf(v, 0.0f) + log1pf(__expf(-fabsf(v)));
            const float xcv = g_xc[(size_t)row * DI + col];
            g_dx[(size_t)row * DI + col] = make_float2(v, v * xcv);
        }
    }
}

// ------------------------------------------------------------------
// selective scan: 16 lanes per channel, one state per lane
// ------------------------------------------------------------------
__global__ void scan_kernel(const float* __restrict__ A_log) {
    const int s = threadIdx.x & 15;
    const int d = blockIdx.x * 16 + (threadIdx.x >> 4);
    const float a = -__expf(A_log[d * DSTATE + s]);
    float h = 0.0f;
    constexpr int PF = 8;
    float2 pd[PF], pb[PF];
#pragma unroll
    for (int i = 0; i < PF; ++i) {
        pd[i] = g_dx[(size_t)i * DI + d];
        pb[i] = g_bc[i * DSTATE + s];
    }
#pragma unroll 4
    for (int t = 0; t < LSEQ; ++t) {
        const int sl = t & (PF - 1);
        const float2 dxv = pd[sl];
        const float2 bcv = pb[sl];
        const int tp = t + PF;
        if (tp < LSEQ) {
            pd[sl] = g_dx[(size_t)tp * DI + d];
            pb[sl] = g_bc[tp * DSTATE + s];
        }
        const float dA = __expf(a * dxv.x);
        h = fmaf(h, dA, dxv.y * bcv.x);
        float p = h * bcv.y;
        p += __shfl_xor_sync(0xffffffffu, p, 1);
        p += __shfl_xor_sync(0xffffffffu, p, 2);
        p += __shfl_xor_sync(0xffffffffu, p, 4);
        p += __shfl_xor_sync(0xffffffffu, p, 8);
        if (s == 0) g_ys[(size_t)t * DI + d] = p;
    }
}

// ------------------------------------------------------------------
// y = (ys + xc*Dp) * silu(z) -> bf16 hi/lo
// ------------------------------------------------------------------
__global__ void ygate_kernel(const float* __restrict__ Dp) {
    const int idx = blockIdx.x * blockDim.x + threadIdx.x;
    const int d = idx & (DI - 1);
    const int t = idx >> 11;
    const float z = g_xz[(size_t)t * (2 * DI) + DI + d];
    const float sig = 1.0f / (1.0f + __expf(-z));
    const float v = fmaf(g_xc[idx], Dp[d], g_ys[idx]) * (z * sig);
    const bf16 hh = __float2bfloat16(v);
    g_y_h[idx] = hh;
    g_y_l[idx] = __float2bfloat16(v - __bfloat162float(hh));
}

// ------------------------------------------------------------------
// launch
// ------------------------------------------------------------------
extern "C" void kernel_launch(void* const* d_in, const int* in_sizes, int n_in,
                              void* d_out, int out_size) {
    const float* x         = (const float*)d_in[0];
    const float* ln1_g     = (const float*)d_in[1];
    const float* ln1_b     = (const float*)d_in[2];
    const float* ln2_g     = (const float*)d_in[3];
    const float* ln2_b     = (const float*)d_in[4];
    const float* in_proj_w = (const float*)d_in[5];
    const float* conv_w    = (const float*)d_in[6];
    const float* conv_b    = (const float*)d_in[7];
    const float* x_proj_w  = (const float*)d_in[8];
    const float* dt_proj_w = (const float*)d_in[9];
    const float* dt_proj_b = (const float*)d_in[10];
    const float* A_log     = (const float*)d_in[11];
    const float* D_param   = (const float*)d_in[12];
    const float* out_proj_w= (const float*)d_in[13];
    const float* ffn_w1    = (const float*)d_in[14];
    const float* ffn_b1    = (const float*)d_in[15];
    const float* ffn_w2    = (const float*)d_in[16];
    const float* ffn_b2    = (const float*)d_in[17];
    float* out = (float*)d_out;

    cudaFuncSetAttribute(tc_gemm, cudaFuncAttributeMaxDynamicSharedMemorySize, SM_GEMM_TOTAL);

#define SYM(p, s) void* p; cudaGetSymbolAddress(&p, s)
    SYM(p_xz, g_xz); SYM(p_xc, g_xc); SYM(p_proj, g_proj); SYM(p_h, g_h); SYM(p_n, g_n);
    SYM(p_hln_h, g_hln_h); SYM(p_hln_l, g_hln_l);
    SYM(p_xc_h, g_xc_h); SYM(p_xc_l, g_xc_l);
    SYM(p_y_h, g_y_h); SYM(p_y_l, g_y_l);
    SYM(p_n_h, g_n_h); SYM(p_n_l, g_n_l);
    SYM(p_f1_h, g_f1_h); SYM(p_f1_l, g_f1_l);
    SYM(p_win_h, g_win_h); SYM(p_win_l, g_win_l);
    SYM(p_wxp_h, g_wxp_h); SYM(p_wxp_l, g_wxp_l);
    SYM(p_wout_h, g_wout_h); SYM(p_wout_l, g_wout_l);
    SYM(p_wf1_h, g_wf1_h); SYM(p_wf1_l, g_wf1_l);
    SYM(p_wf2_h, g_wf2_h); SYM(p_wf2_l, g_wf2_l);
#undef SYM

    // weight conversions
    cvt_hl<<<(2 * DI * DMODEL + 255) / 256, 256>>>(in_proj_w, (bf16*)p_win_h, (bf16*)p_win_l, 2 * DI * DMODEL);
    cvt_hl<<<(NPROJ * DI + 255) / 256, 256>>>(x_proj_w, (bf16*)p_wxp_h, (bf16*)p_wxp_l, NPROJ * DI);
    cvt_hl<<<(DMODEL * DI + 255) / 256, 256>>>(out_proj_w, (bf16*)p_wout_h, (bf16*)p_wout_l, DMODEL * DI);
    cvt_hl<<<(HIDF * DMODEL + 255) / 256, 256>>>(ffn_w1, (bf16*)p_wf1_h, (bf16*)p_wf1_l, HIDF * DMODEL);
    cvt_hl<<<(DMODEL * HIDF + 255) / 256, 256>>>(ffn_w2, (bf16*)p_wf2_h, (bf16*)p_wf2_l, DMODEL * HIDF);

    // 1) LN1 -> hln hi/lo
    ln_kernel<<<LSEQ, 256>>>(x, ln1_g, ln1_b, nullptr, (bf16*)p_hln_h, (bf16*)p_hln_l);

    // 2) xz = hln @ in_proj_w^T   [2048, 4096]
    tc_gemm<<<dim3(32, 16), 256, SM_GEMM_TOTAL>>>(
        (bf16*)p_hln_h, (bf16*)p_hln_l, (bf16*)p_win_h, (bf16*)p_win_l,
        (float*)p_xz, nullptr, nullptr, 2 * DI, 2 * DI, DMODEL, 0,
        nullptr, nullptr, 0, nullptr, 0);

    // 3) conv + silu -> xc (fp32 + hi/lo)
    conv_silu_kernel<<<(LSEQ * DI) / 256, 256>>>(conv_w, conv_b);

    // 4) proj = xc @ x_proj_w^T   [2048, 96]
    tc_gemm<<<dim3(1, 16), 256, SM_GEMM_TOTAL>>>(
        (bf16*)p_xc_h, (bf16*)p_xc_l, (bf16*)p_wxp_h, (bf16*)p_wxp_l,
        (float*)p_proj, nullptr, nullptr, NPROJ, NPROJ, DI, 0,
        nullptr, nullptr, 0, nullptr, 0);

    // 5) pack (B, C)
    pack_bc_kernel<<<(LSEQ * DSTATE) / 256, 256>>>();

    // 6) delta = softplus(dt @ dt_proj_w^T + b); dx = (delta, delta*xc)
    delta_gemm<<<dim3(DI / 128, LSEQ / 128), 256>>>((const float*)p_proj, dt_proj_w, dt_proj_b);

    // 7) selective scan
    scan_kernel<<<DI / 16, 256>>>(A_log);

    // 8) y gate -> y hi/lo
    ygate_kernel<<<(LSEQ * DI) / 256, 256>>>(D_param);

    // 9) h = y @ out_proj_w^T + x   [2048, 1024]
    tc_gemm<<<dim3(8, 16), 256, SM_GEMM_TOTAL>>>(
        (bf16*)p_y_h, (bf16*)p_y_l, (bf16*)p_wout_h, (bf16*)p_wout_l,
        (float*)p_h, nullptr, nullptr, DMODEL, DMODEL, DI, 1,
        nullptr, x, DMODEL, nullptr, 0);

    // 10) LN2 -> n (fp32 + hi/lo)
    ln_kernel<<<LSEQ, 256>>>((const float*)p_h, ln2_g, ln2_b, (float*)p_n, (bf16*)p_n_h, (bf16*)p_n_l);

    // 11) f1 = relu(n @ ffn_w1^T + b1) -> bf16 hi/lo   [2048, 4096]
    tc_gemm<<<dim3(32, 16), 256, SM_GEMM_TOTAL>>>(
        (bf16*)p_n_h, (bf16*)p_n_l, (bf16*)p_wf1_h, (bf16*)p_wf1_l,
        nullptr, (bf16*)p_f1_h, (bf16*)p_f1_l, HIDF, HIDF, DMODEL, 2,
        ffn_b1, nullptr, 0, nullptr, 0);

    // 12) out = f1 @ ffn_w2^T + b2 + n + h   [2048, 1024]
    tc_gemm<<<dim3(8, 16), 256, SM_GEMM_TOTAL>>>(
        (bf16*)p_f1_h, (bf16*)p_f1_l, (bf16*)p_wf2_h, (bf16*)p_wf2_l,
        out, nullptr, nullptr, DMODEL, DMODEL, HIDF, 3,
        ffn_b2, (const float*)p_n, DMODEL, (const float*)p_h, DMODEL);
}

// round 5
// speedup vs baseline: 2.1106x; 1.2172x over previous
#include <cuda_runtime.h>
#include <cuda_fp16.h>
#include <cstdint>
#include <cstddef>

#define LSEQ 2048
#define DMODEL 1024
#define DI 2048
#define DSTATE 16
#define DTRANK 64
#define HIDF 4096
#define NPROJ 96

// ------------------------------------------------------------------
// scratch (device globals; no allocation allowed)
// ------------------------------------------------------------------
__device__ float  g_xz[LSEQ * 2 * DI];
__device__ float  g_xc[LSEQ * DI];
__device__ float  g_proj[LSEQ * NPROJ];
__device__ float2 g_dx[LSEQ * DI];          // (delta, delta*xc)
__device__ float2 g_bc[LSEQ * DSTATE];      // (B, C)
__device__ float  g_ys[LSEQ * DI];
__device__ float  g_h[LSEQ * DMODEL];
__device__ float  g_n[LSEQ * DMODEL];

// fp16 activations (single precision level — no lo needed)
__device__ __half g_hln_h[LSEQ * DMODEL];
__device__ __half g_xc_h[LSEQ * DI];
__device__ __half g_y_h[LSEQ * DI];
__device__ __half g_n_h[LSEQ * DMODEL];
__device__ __half g_f1_h[LSEQ * HIDF];

// fp16 hi/lo weights
__device__ __half g_win_h[2 * DI * DMODEL], g_win_l[2 * DI * DMODEL];
__device__ __half g_wxp_h[NPROJ * DI],      g_wxp_l[NPROJ * DI];
__device__ __half g_wout_h[DMODEL * DI],    g_wout_l[DMODEL * DI];
__device__ __half g_wf1_h[HIDF * DMODEL],   g_wf1_l[HIDF * DMODEL];
__device__ __half g_wf2_h[DMODEL * HIDF],   g_wf2_l[DMODEL * HIDF];

// ------------------------------------------------------------------
// PTX helpers
// ------------------------------------------------------------------
__device__ __forceinline__ uint32_t smem_u32(const void* p) {
    uint32_t a;
    asm("{ .reg .u64 t; cvta.to.shared.u64 t, %1; cvt.u32.u64 %0, t; }" : "=r"(a) : "l"(p));
    return a;
}
__device__ __forceinline__ void cp16(uint32_t dst, const void* src, bool p) {
    int sz = p ? 16 : 0;
    asm volatile("cp.async.cg.shared.global [%0], [%1], 16, %2;"
                 :: "r"(dst), "l"(src), "r"(sz) : "memory");
}
__device__ __forceinline__ void cp_commit() {
    asm volatile("cp.async.commit_group;" ::: "memory");
}
__device__ __forceinline__ void cp_wait1() {
    asm volatile("cp.async.wait_group 1;" ::: "memory");
}
__device__ __forceinline__ void ldsm_x4(uint32_t addr, uint32_t* r) {
    asm volatile("ldmatrix.sync.aligned.m8n8.x4.shared.b16 {%0,%1,%2,%3}, [%4];"
                 : "=r"(r[0]), "=r"(r[1]), "=r"(r[2]), "=r"(r[3]) : "r"(addr));
}
__device__ __forceinline__ void mma_f16(float* c, const uint32_t* a, const uint32_t* b) {
    asm volatile(
        "mma.sync.aligned.m16n8k16.row.col.f32.f16.f16.f32 "
        "{%0,%1,%2,%3}, {%4,%5,%6,%7}, {%8,%9}, {%0,%1,%2,%3};"
        : "+f"(c[0]), "+f"(c[1]), "+f"(c[2]), "+f"(c[3])
        : "r"(a[0]), "r"(a[1]), "r"(a[2]), "r"(a[3]), "r"(b[0]), "r"(b[1]));
}
__device__ __forceinline__ uint32_t sw128(uint32_t bo) { return bo ^ ((bo >> 3) & 0x70); }

// ------------------------------------------------------------------
// GEMM: C[M,N] = A[M,K] @ W[N,K]^T, A fp16, W fp16 hi/lo (2-term comp).
// 128x128 tile, k-chunk 64, 3-stage cp.async ring, 256 thr (8 warps 32x64).
// modes: 0 store f32 | 1 +res1 f32 | 2 bias+relu -> fp16 | 3 bias+res1+res2 f32
// stage: A 16KB | Bh 16KB | Bl 16KB = 48KB; 3 stages = 144KB
// ------------------------------------------------------------------
#define STAGE_BYTES 49152
#define SM_GEMM_TOTAL (3 * STAGE_BYTES)

__device__ __forceinline__ void stage_load(
    uint32_t st, const __half* __restrict__ A,
    const __half* __restrict__ Bh, const __half* __restrict__ Bl,
    int bm, int bn, int K, int k0, int bvalid, int tid) {
#pragma unroll
    for (int i = 0; i < 4; ++i) {
        const int idx = tid + i * 256;     // 0..1023
        const int r = idx >> 3;            // row 0..127
        const int q = idx & 7;             // 16B quad in 128B row
        const uint32_t sw = sw128(r * 128 + q * 16);
        cp16(st + sw, A + (size_t)(bm + r) * K + k0 + q * 8, true);
        const bool p = r < bvalid;
        const size_t boff = (size_t)(bn + r) * K + k0 + q * 8;
        cp16(st + 16384 + sw, Bh + boff, p);
        cp16(st + 32768 + sw, Bl + boff, p);
    }
}

__global__ __launch_bounds__(256, 1)
void tc_gemm(const __half* __restrict__ A,
             const __half* __restrict__ Bh, const __half* __restrict__ Bl,
             float* __restrict__ C, __half* __restrict__ Oh,
             int ldc, int N, int K, int mode,
             const float* __restrict__ bias,
             const float* __restrict__ res1, int ldr1,
             const float* __restrict__ res2, int ldr2) {
    extern __shared__ char smem[];
    const uint32_t sb = smem_u32(smem);
    const int tid = threadIdx.x;
    const int wid = tid >> 5, lid = tid & 31;
    const int bm = blockIdx.y * 128;
    const int bn = blockIdx.x * 128;
    const int wm = (wid & 3) * 32;
    const int wn = (wid >> 2) * 64;
    const int bvalid = (N - bn) < 128 ? (N - bn) : 128;
    const int nch = K >> 6;

    float acc[2][8][4];
#pragma unroll
    for (int mf = 0; mf < 2; ++mf)
#pragma unroll
        for (int nf = 0; nf < 8; ++nf)
#pragma unroll
            for (int v = 0; v < 4; ++v) acc[mf][nf][v] = 0.0f;

    const int mat = lid >> 3;
    const int lrow = lid & 7;
    const int rowA = wm + (mat & 1) * 8 + lrow;
    const int kqA = (mat >> 1);
    const int rowB = wn + (mat >> 1) * 8 + lrow;
    const int kqB = (mat & 1);

    stage_load(sb + 0 * STAGE_BYTES, A, Bh, Bl, bm, bn, K, 0, bvalid, tid);
    cp_commit();
    if (nch > 1)
        stage_load(sb + 1 * STAGE_BYTES, A, Bh, Bl, bm, bn, K, 64, bvalid, tid);
    cp_commit();

    for (int c = 0; c < nch; ++c) {
        cp_wait1();
        __syncthreads();
        if (c + 2 < nch)
            stage_load(sb + ((c + 2) % 3) * STAGE_BYTES, A, Bh, Bl,
                       bm, bn, K, (c + 2) * 64, bvalid, tid);
        cp_commit();

        const uint32_t base = sb + (c % 3) * STAGE_BYTES;
#pragma unroll
        for (int ks = 0; ks < 4; ++ks) {
            uint32_t ah[2][4], bhf[16], blf[16];
#pragma unroll
            for (int mf = 0; mf < 2; ++mf) {
                const uint32_t bo = (uint32_t)(rowA + mf * 16) * 128 + ks * 32 + kqA * 16;
                ldsm_x4(base + sw128(bo), ah[mf]);
            }
#pragma unroll
            for (int p = 0; p < 4; ++p) {
                const uint32_t bo = (uint32_t)(rowB + p * 16) * 128 + ks * 32 + kqB * 16;
                const uint32_t sw = sw128(bo);
                ldsm_x4(base + 16384 + sw, &bhf[p * 4]);
                ldsm_x4(base + 32768 + sw, &blf[p * 4]);
            }
#pragma unroll
            for (int mf = 0; mf < 2; ++mf)
#pragma unroll
                for (int nf = 0; nf < 8; ++nf) {
                    mma_f16(acc[mf][nf], ah[mf], &bhf[nf * 2]);
                    mma_f16(acc[mf][nf], ah[mf], &blf[nf * 2]);
                }
        }
    }

    const int erow0 = bm + wm + (lid >> 2);
    const int ecol0 = bn + wn + (lid & 3) * 2;
#pragma unroll
    for (int mf = 0; mf < 2; ++mf)
#pragma unroll
        for (int nf = 0; nf < 8; ++nf)
#pragma unroll
            for (int half = 0; half < 2; ++half) {
                const int row = erow0 + mf * 16 + half * 8;
                const int col = ecol0 + nf * 8;
                if (col >= N) continue;
                float v0 = acc[mf][nf][half * 2 + 0];
                float v1 = acc[mf][nf][half * 2 + 1];
                if (mode == 0) {
                    *(float2*)(C + (size_t)row * ldc + col) = make_float2(v0, v1);
                } else if (mode == 1) {
                    const float2 rr = *(const float2*)(res1 + (size_t)row * ldr1 + col);
                    *(float2*)(C + (size_t)row * ldc + col) = make_float2(v0 + rr.x, v1 + rr.y);
                } else if (mode == 2) {
                    const float2 bb = *(const float2*)(bias + col);
                    v0 = fmaxf(v0 + bb.x, 0.f);
                    v1 = fmaxf(v1 + bb.y, 0.f);
                    *(__half2*)(Oh + (size_t)row * ldc + col) =
                        __half2(__float2half_rn(v0), __float2half_rn(v1));
                } else {
                    const float2 bb = *(const float2*)(bias + col);
                    const float2 r1 = *(const float2*)(res1 + (size_t)row * ldr1 + col);
                    const float2 r2 = *(const float2*)(res2 + (size_t)row * ldr2 + col);
                    *(float2*)(C + (size_t)row * ldc + col) =
                        make_float2(v0 + bb.x + r1.x + r2.x, v1 + bb.y + r1.y + r2.y);
                }
            }
}

// ------------------------------------------------------------------
// LayerNorm (D=1024): optional fp32 out + fp16 out
// ------------------------------------------------------------------
__global__ void ln_kernel(const float* __restrict__ x, const float* __restrict__ g,
                          const float* __restrict__ b, float* __restrict__ outf,
                          __half* __restrict__ oh) {
    __shared__ float rs[8], rq[8];
    const int tid = threadIdx.x;
    const size_t base = (size_t)blockIdx.x * DMODEL;
    float4 xv = *(const float4*)(x + base + tid * 4);
    float s = xv.x + xv.y + xv.z + xv.w;
    float q = xv.x * xv.x + xv.y * xv.y + xv.z * xv.z + xv.w * xv.w;
#pragma unroll
    for (int o = 16; o > 0; o >>= 1) {
        s += __shfl_xor_sync(0xffffffffu, s, o);
        q += __shfl_xor_sync(0xffffffffu, q, o);
    }
    if ((tid & 31) == 0) { rs[tid >> 5] = s; rq[tid >> 5] = q; }
    __syncthreads();
    s = rs[0] + rs[1] + rs[2] + rs[3] + rs[4] + rs[5] + rs[6] + rs[7];
    q = rq[0] + rq[1] + rq[2] + rq[3] + rq[4] + rq[5] + rq[6] + rq[7];
    const float mu = s * (1.0f / DMODEL);
    const float var = q * (1.0f / DMODEL) - mu * mu;
    const float rstd = rsqrtf(var + 1e-5f);
    float4 gv = *(const float4*)(g + tid * 4);
    float4 bv = *(const float4*)(b + tid * 4);
    float o0 = (xv.x - mu) * rstd * gv.x + bv.x;
    float o1 = (xv.y - mu) * rstd * gv.y + bv.y;
    float o2 = (xv.z - mu) * rstd * gv.z + bv.z;
    float o3 = (xv.w - mu) * rstd * gv.w + bv.w;
    if (outf) *(float4*)(outf + base + tid * 4) = make_float4(o0, o1, o2, o3);
    __half2* ph = (__half2*)(oh + base + tid * 4);
    ph[0] = __half2(__float2half_rn(o0), __float2half_rn(o1));
    ph[1] = __half2(__float2half_rn(o2), __float2half_rn(o3));
}

// ------------------------------------------------------------------
// weight fp32 -> fp16 hi/lo, vectorized (4 elems/thread)
// ------------------------------------------------------------------
__global__ void cvt_hl(const float4* __restrict__ src, __half2* __restrict__ h,
                       __half2* __restrict__ l, int n4) {
    const int i = blockIdx.x * blockDim.x + threadIdx.x;
    if (i < n4) {
        const float4 v = src[i];
        const __half h0 = __float2half_rn(v.x), h1 = __float2half_rn(v.y);
        const __half h2 = __float2half_rn(v.z), h3 = __float2half_rn(v.w);
        h[2 * i + 0] = __half2(h0, h1);
        h[2 * i + 1] = __half2(h2, h3);
        l[2 * i + 0] = __half2(__float2half_rn(v.x - __half2float(h0)),
                               __float2half_rn(v.y - __half2float(h1)));
        l[2 * i + 1] = __half2(__float2half_rn(v.z - __half2float(h2)),
                               __float2half_rn(v.w - __half2float(h3)));
    }
}

// ------------------------------------------------------------------
// causal depthwise conv + SiLU -> xc fp32 + fp16
// ------------------------------------------------------------------
__global__ void conv_silu_kernel(const float* __restrict__ conv_w, const float* __restrict__ conv_b) {
    const int idx = blockIdx.x * blockDim.x + threadIdx.x;
    const int d = idx & (DI - 1);
    const int t = idx >> 11;
    float acc = conv_b[d];
#pragma unroll
    for (int k = 0; k < 4; ++k) {
        const int tt = t + k - 3;
        if (tt >= 0) acc = fmaf(g_xz[(size_t)tt * (2 * DI) + d], conv_w[d * 4 + k], acc);
    }
    const float v = acc / (1.0f + __expf(-acc));
    g_xc[idx] = v;
    g_xc_h[idx] = __float2half_rn(v);
}

// ------------------------------------------------------------------
// pack (B, C) from proj
// ------------------------------------------------------------------
__global__ void pack_bc_kernel() {
    const int i = blockIdx.x * blockDim.x + threadIdx.x;   // L*16
    const int t = i >> 4, s = i & 15;
    g_bc[i] = make_float2(g_proj[t * NPROJ + DTRANK + s],
                          g_proj[t * NPROJ + DTRANK + DSTATE + s]);
}

// ------------------------------------------------------------------
// delta GEMM (SIMT, K=64): dx = (softplus(dt @ Wdt^T + b), delta*xc)
// ------------------------------------------------------------------
__global__ __launch_bounds__(256, 2)
void delta_gemm(const float* __restrict__ P, const float* __restrict__ W,
                const float* __restrict__ bias) {
    __shared__ float As[8][128];
    __shared__ float Bs[8][128];
    const int tid = threadIdx.x;
    const int bm = blockIdx.y * 128;
    const int bn = blockIdx.x * 128;
    const int aRow = tid >> 1, aCol = (tid & 1) * 4;
    const int tx = tid & 15, ty = tid >> 4;
    float acc[8][8];
#pragma unroll
    for (int i = 0; i < 8; ++i)
#pragma unroll
        for (int j = 0; j < 8; ++j) acc[i][j] = 0.0f;
    for (int k0 = 0; k0 < 64; k0 += 8) {
        float4 av = *(const float4*)(P + (size_t)(bm + aRow) * NPROJ + k0 + aCol);
        float4 bv = *(const float4*)(W + (size_t)(bn + aRow) * 64 + k0 + aCol);
        __syncthreads();
        As[aCol + 0][aRow] = av.x; As[aCol + 1][aRow] = av.y;
        As[aCol + 2][aRow] = av.z; As[aCol + 3][aRow] = av.w;
        Bs[aCol + 0][aRow] = bv.x; Bs[aCol + 1][aRow] = bv.y;
        Bs[aCol + 2][aRow] = bv.z; Bs[aCol + 3][aRow] = bv.w;
        __syncthreads();
#pragma unroll
        for (int kk = 0; kk < 8; ++kk) {
            float rm[8], rn[8];
            *(float4*)&rm[0] = *(const float4*)&As[kk][ty * 8];
            *(float4*)&rm[4] = *(const float4*)&As[kk][ty * 8 + 4];
            *(float4*)&rn[0] = *(const float4*)&Bs[kk][tx * 8];
            *(float4*)&rn[4] = *(const float4*)&Bs[kk][tx * 8 + 4];
#pragma unroll
            for (int i = 0; i < 8; ++i)
#pragma unroll
                for (int j = 0; j < 8; ++j) acc[i][j] = fmaf(rm[i], rn[j], acc[i][j]);
        }
    }
#pragma unroll
    for (int i = 0; i < 8; ++i) {
        const int row = bm + ty * 8 + i;
#pragma unroll
        for (int j = 0; j < 8; ++j) {
            const int col = bn + tx * 8 + j;
            float v = acc[i][j] + bias[col];
            v = fmaxf(v, 0.0f) + log1pf(__expf(-fabsf(v)));
            const float xcv = g_xc[(size_t)row * DI + col];
            g_dx[(size_t)row * DI + col] = make_float2(v, v * xcv);
        }
    }
}

// ------------------------------------------------------------------
// selective scan: 16 lanes per channel, one state per lane
// ------------------------------------------------------------------
__global__ void scan_kernel(const float* __restrict__ A_log) {
    const int s = threadIdx.x & 15;
    const int d = blockIdx.x * 16 + (threadIdx.x >> 4);
    const float a = -__expf(A_log[d * DSTATE + s]);
    float h = 0.0f;
    constexpr int PF = 8;
    float2 pd[PF], pb[PF];
#pragma unroll
    for (int i = 0; i < PF; ++i) {
        pd[i] = g_dx[(size_t)i * DI + d];
        pb[i] = g_bc[i * DSTATE + s];
    }
#pragma unroll 4
    for (int t = 0; t < LSEQ; ++t) {
        const int sl = t & (PF - 1);
        const float2 dxv = pd[sl];
        const float2 bcv = pb[sl];
        const int tp = t + PF;
        if (tp < LSEQ) {
            pd[sl] = g_dx[(size_t)tp * DI + d];
            pb[sl] = g_bc[tp * DSTATE + s];
        }
        const float dA = __expf(a * dxv.x);
        h = fmaf(h, dA, dxv.y * bcv.x);
        float p = h * bcv.y;
        p += __shfl_xor_sync(0xffffffffu, p, 1);
        p += __shfl_xor_sync(0xffffffffu, p, 2);
        p += __shfl_xor_sync(0xffffffffu, p, 4);
        p += __shfl_xor_sync(0xffffffffu, p, 8);
        if (s == 0) g_ys[(size_t)t * DI + d] = p;
    }
}

// ------------------------------------------------------------------
// y = (ys + xc*Dp) * silu(z) -> fp16
// ------------------------------------------------------------------
__global__ void ygate_kernel(const float* __restrict__ Dp) {
    const int idx = blockIdx.x * blockDim.x + threadIdx.x;
    const int d = idx & (DI - 1);
    const int t = idx >> 11;
    const float z = g_xz[(size_t)t * (2 * DI) + DI + d];
    const float sig = 1.0f / (1.0f + __expf(-z));
    const float v = fmaf(g_xc[idx], Dp[d], g_ys[idx]) * (z * sig);
    g_y_h[idx] = __float2half_rn(v);
}

// ------------------------------------------------------------------
// launch
// ------------------------------------------------------------------
extern "C" void kernel_launch(void* const* d_in, const int* in_sizes, int n_in,
                              void* d_out, int out_size) {
    const float* x         = (const float*)d_in[0];
    const float* ln1_g     = (const float*)d_in[1];
    const float* ln1_b     = (const float*)d_in[2];
    const float* ln2_g     = (const float*)d_in[3];
    const float* ln2_b     = (const float*)d_in[4];
    const float* in_proj_w = (const float*)d_in[5];
    const float* conv_w    = (const float*)d_in[6];
    const float* conv_b    = (const float*)d_in[7];
    const float* x_proj_w  = (const float*)d_in[8];
    const float* dt_proj_w = (const float*)d_in[9];
    const float* dt_proj_b = (const float*)d_in[10];
    const float* A_log     = (const float*)d_in[11];
    const float* D_param   = (const float*)d_in[12];
    const float* out_proj_w= (const float*)d_in[13];
    const float* ffn_w1    = (const float*)d_in[14];
    const float* ffn_b1    = (const float*)d_in[15];
    const float* ffn_w2    = (const float*)d_in[16];
    const float* ffn_b2    = (const float*)d_in[17];
    float* out = (float*)d_out;

    cudaFuncSetAttribute(tc_gemm, cudaFuncAttributeMaxDynamicSharedMemorySize, SM_GEMM_TOTAL);

#define SYM(p, s) void* p; cudaGetSymbolAddress(&p, s)
    SYM(p_xz, g_xz); SYM(p_xc, g_xc); SYM(p_proj, g_proj); SYM(p_h, g_h); SYM(p_n, g_n);
    SYM(p_hln_h, g_hln_h);
    SYM(p_xc_h, g_xc_h);
    SYM(p_y_h, g_y_h);
    SYM(p_n_h, g_n_h);
    SYM(p_f1_h, g_f1_h);
    SYM(p_win_h, g_win_h); SYM(p_win_l, g_win_l);
    SYM(p_wxp_h, g_wxp_h); SYM(p_wxp_l, g_wxp_l);
    SYM(p_wout_h, g_wout_h); SYM(p_wout_l, g_wout_l);
    SYM(p_wf1_h, g_wf1_h); SYM(p_wf1_l, g_wf1_l);
    SYM(p_wf2_h, g_wf2_h); SYM(p_wf2_l, g_wf2_l);
#undef SYM

    // weight conversions (vectorized x4)
    cvt_hl<<<(2 * DI * DMODEL / 4 + 255) / 256, 256>>>((const float4*)in_proj_w, (__half2*)p_win_h, (__half2*)p_win_l, 2 * DI * DMODEL / 4);
    cvt_hl<<<(NPROJ * DI / 4 + 255) / 256, 256>>>((const float4*)x_proj_w, (__half2*)p_wxp_h, (__half2*)p_wxp_l, NPROJ * DI / 4);
    cvt_hl<<<(DMODEL * DI / 4 + 255) / 256, 256>>>((const float4*)out_proj_w, (__half2*)p_wout_h, (__half2*)p_wout_l, DMODEL * DI / 4);
    cvt_hl<<<(HIDF * DMODEL / 4 + 255) / 256, 256>>>((const float4*)ffn_w1, (__half2*)p_wf1_h, (__half2*)p_wf1_l, HIDF * DMODEL / 4);
    cvt_hl<<<(DMODEL * HIDF / 4 + 255) / 256, 256>>>((const float4*)ffn_w2, (__half2*)p_wf2_h, (__half2*)p_wf2_l, DMODEL * HIDF / 4);

    // 1) LN1 -> hln fp16
    ln_kernel<<<LSEQ, 256>>>(x, ln1_g, ln1_b, nullptr, (__half*)p_hln_h);

    // 2) xz = hln @ in_proj_w^T   [2048, 4096]
    tc_gemm<<<dim3(32, 16), 256, SM_GEMM_TOTAL>>>(
        (__half*)p_hln_h, (__half*)p_win_h, (__half*)p_win_l,
        (float*)p_xz, nullptr, 2 * DI, 2 * DI, DMODEL, 0,
        nullptr, nullptr, 0, nullptr, 0);

    // 3) conv + silu -> xc (fp32 + fp16)
    conv_silu_kernel<<<(LSEQ * DI) / 256, 256>>>(conv_w, conv_b);

    // 4) proj = xc @ x_proj_w^T   [2048, 96]
    tc_gemm<<<dim3(1, 16), 256, SM_GEMM_TOTAL>>>(
        (__half*)p_xc_h, (__half*)p_wxp_h, (__half*)p_wxp_l,
        (float*)p_proj, nullptr, NPROJ, NPROJ, DI, 0,
        nullptr, nullptr, 0, nullptr, 0);

    // 5) pack (B, C)
    pack_bc_kernel<<<(LSEQ * DSTATE) / 256, 256>>>();

    // 6) delta = softplus(dt @ dt_proj_w^T + b); dx = (delta, delta*xc)
    delta_gemm<<<dim3(DI / 128, LSEQ / 128), 256>>>((const float*)p_proj, dt_proj_w, dt_proj_b);

    // 7) selective scan
    scan_kernel<<<DI / 16, 256>>>(A_log);

    // 8) y gate -> y fp16
    ygate_kernel<<<(LSEQ * DI) / 256, 256>>>(D_param);

    // 9) h = y @ out_proj_w^T + x   [2048, 1024]
    tc_gemm<<<dim3(8, 16), 256, SM_GEMM_TOTAL>>>(
        (__half*)p_y_h, (__half*)p_wout_h, (__half*)p_wout_l,
        (float*)p_h, nullptr, DMODEL, DMODEL, DI, 1,
        nullptr, x, DMODEL, nullptr, 0);

    // 10) LN2 -> n (fp32 + fp16)
    ln_kernel<<<LSEQ, 256>>>((const float*)p_h, ln2_g, ln2_b, (float*)p_n, (__half*)p_n_h);

    // 11) f1 = relu(n @ ffn_w1^T + b1) -> fp16   [2048, 4096]
    tc_gemm<<<dim3(32, 16), 256, SM_GEMM_TOTAL>>>(
        (__half*)p_n_h, (__half*)p_wf1_h, (__half*)p_wf1_l,
        nullptr, (__half*)p_f1_h, HIDF, HIDF, DMODEL, 2,
        ffn_b1, nullptr, 0, nullptr, 0);

    // 12) out = f1 @ ffn_w2^T + b2 + n + h   [2048, 1024]
    tc_gemm<<<dim3(8, 16), 256, SM_GEMM_TOTAL>>>(
        (__half*)p_f1_h, (__half*)p_wf2_h, (__half*)p_wf2_l,
        out, nullptr, DMODEL, DMODEL, HIDF, 3,
        ffn_b2, (const float*)p_n, DMODEL, (const float*)p_h, DMODEL);
}

// round 6
// speedup vs baseline: 2.4525x; 1.1620x over previous
#include <cuda_runtime.h>
#include <cuda_fp16.h>
#include <cstdint>
#include <cstddef>

#define LSEQ 2048
#define DMODEL 1024
#define DI 2048
#define DSTATE 16
#define DTRANK 64
#define HIDF 4096
#define NPROJ 96

// ------------------------------------------------------------------
// scratch (device globals; no allocation allowed)
// ------------------------------------------------------------------
__device__ float  g_xz[LSEQ * 2 * DI];
__device__ float  g_xc[LSEQ * DI];
__device__ float  g_proj[LSEQ * NPROJ];
__device__ float2 g_dx[LSEQ * DI];          // (delta, delta*xc)
__device__ float2 g_bc[LSEQ * DSTATE];      // (B, C)
__device__ float  g_ys[LSEQ * DI];
__device__ float  g_h[LSEQ * DMODEL];
__device__ float  g_n[LSEQ * DMODEL];

// fp16 activations
__device__ __half g_hln_h[LSEQ * DMODEL];
__device__ __half g_xc_h[LSEQ * DI];
__device__ __half g_y_h[LSEQ * DI];
__device__ __half g_n_h[LSEQ * DMODEL];
__device__ __half g_f1_h[LSEQ * HIDF];

// fp16 weights (single precision level)
__device__ __half g_win_h[2 * DI * DMODEL];
__device__ __half g_wxp_h[NPROJ * DI];
__device__ __half g_wout_h[DMODEL * DI];
__device__ __half g_wf1_h[HIDF * DMODEL];
__device__ __half g_wf2_h[DMODEL * HIDF];

// ------------------------------------------------------------------
// PTX helpers
// ------------------------------------------------------------------
__device__ __forceinline__ uint32_t smem_u32(const void* p) {
    uint32_t a;
    asm("{ .reg .u64 t; cvta.to.shared.u64 t, %1; cvt.u32.u64 %0, t; }" : "=r"(a) : "l"(p));
    return a;
}
__device__ __forceinline__ void cp16(uint32_t dst, const void* src, bool p) {
    int sz = p ? 16 : 0;
    asm volatile("cp.async.cg.shared.global [%0], [%1], 16, %2;"
                 :: "r"(dst), "l"(src), "r"(sz) : "memory");
}
__device__ __forceinline__ void cp_commit() {
    asm volatile("cp.async.commit_group;" ::: "memory");
}
__device__ __forceinline__ void cp_wait1() {
    asm volatile("cp.async.wait_group 1;" ::: "memory");
}
__device__ __forceinline__ void ldsm_x4(uint32_t addr, uint32_t* r) {
    asm volatile("ldmatrix.sync.aligned.m8n8.x4.shared.b16 {%0,%1,%2,%3}, [%4];"
                 : "=r"(r[0]), "=r"(r[1]), "=r"(r[2]), "=r"(r[3]) : "r"(addr));
}
__device__ __forceinline__ void mma_f16(float* c, const uint32_t* a, const uint32_t* b) {
    asm volatile(
        "mma.sync.aligned.m16n8k16.row.col.f32.f16.f16.f32 "
        "{%0,%1,%2,%3}, {%4,%5,%6,%7}, {%8,%9}, {%0,%1,%2,%3};"
        : "+f"(c[0]), "+f"(c[1]), "+f"(c[2]), "+f"(c[3])
        : "r"(a[0]), "r"(a[1]), "r"(a[2]), "r"(a[3]), "r"(b[0]), "r"(b[1]));
}
__device__ __forceinline__ uint32_t sw128(uint32_t bo) { return bo ^ ((bo >> 3) & 0x70); }

// ------------------------------------------------------------------
// GEMM: C[M,N] = A[M,K] @ W[N,K]^T, plain fp16 operands, fp32 accum.
// 128x128 tile, k-chunk 64, 3-stage cp.async ring, 256 thr (8 warps 32x64).
// modes: 0 store f32 | 1 +res1 f32 | 2 bias+relu -> fp16 | 3 bias+res1+res2 f32
// stage: A 16KB | B 16KB = 32KB; 3 stages = 96KB -> 2 CTAs/SM
// ------------------------------------------------------------------
#define STAGE_BYTES 32768
#define SM_GEMM_TOTAL (3 * STAGE_BYTES)

__device__ __forceinline__ void stage_load(
    uint32_t st, const __half* __restrict__ A, const __half* __restrict__ B,
    int bm, int bn, int K, int k0, int bvalid, int tid) {
#pragma unroll
    for (int i = 0; i < 4; ++i) {
        const int idx = tid + i * 256;     // 0..1023
        const int r = idx >> 3;            // row 0..127
        const int q = idx & 7;             // 16B quad in 128B row
        const uint32_t sw = sw128(r * 128 + q * 16);
        cp16(st + sw, A + (size_t)(bm + r) * K + k0 + q * 8, true);
        cp16(st + 16384 + sw, B + (size_t)(bn + r) * K + k0 + q * 8, r < bvalid);
    }
}

__global__ __launch_bounds__(256, 2)
void tc_gemm(const __half* __restrict__ A, const __half* __restrict__ B,
             float* __restrict__ C, __half* __restrict__ Oh,
             int ldc, int N, int K, int mode,
             const float* __restrict__ bias,
             const float* __restrict__ res1, int ldr1,
             const float* __restrict__ res2, int ldr2) {
    extern __shared__ char smem[];
    const uint32_t sb = smem_u32(smem);
    const int tid = threadIdx.x;
    const int wid = tid >> 5, lid = tid & 31;
    const int bm = blockIdx.y * 128;
    const int bn = blockIdx.x * 128;
    const int wm = (wid & 3) * 32;
    const int wn = (wid >> 2) * 64;
    const int bvalid = (N - bn) < 128 ? (N - bn) : 128;
    const int nch = K >> 6;

    float acc[2][8][4];
#pragma unroll
    for (int mf = 0; mf < 2; ++mf)
#pragma unroll
        for (int nf = 0; nf < 8; ++nf)
#pragma unroll
            for (int v = 0; v < 4; ++v) acc[mf][nf][v] = 0.0f;

    const int mat = lid >> 3;
    const int lrow = lid & 7;
    const int rowA = wm + (mat & 1) * 8 + lrow;
    const int kqA = (mat >> 1);
    const int rowB = wn + (mat >> 1) * 8 + lrow;
    const int kqB = (mat & 1);

    stage_load(sb + 0 * STAGE_BYTES, A, B, bm, bn, K, 0, bvalid, tid);
    cp_commit();
    if (nch > 1)
        stage_load(sb + 1 * STAGE_BYTES, A, B, bm, bn, K, 64, bvalid, tid);
    cp_commit();

    for (int c = 0; c < nch; ++c) {
        cp_wait1();
        __syncthreads();
        if (c + 2 < nch)
            stage_load(sb + ((c + 2) % 3) * STAGE_BYTES, A, B,
                       bm, bn, K, (c + 2) * 64, bvalid, tid);
        cp_commit();

        const uint32_t base = sb + (c % 3) * STAGE_BYTES;
#pragma unroll
        for (int ks = 0; ks < 4; ++ks) {
            uint32_t ah[2][4], bf[16];
#pragma unroll
            for (int mf = 0; mf < 2; ++mf) {
                const uint32_t bo = (uint32_t)(rowA + mf * 16) * 128 + ks * 32 + kqA * 16;
                ldsm_x4(base + sw128(bo), ah[mf]);
            }
#pragma unroll
            for (int p = 0; p < 4; ++p) {
                const uint32_t bo = (uint32_t)(rowB + p * 16) * 128 + ks * 32 + kqB * 16;
                ldsm_x4(base + 16384 + sw128(bo), &bf[p * 4]);
            }
#pragma unroll
            for (int mf = 0; mf < 2; ++mf)
#pragma unroll
                for (int nf = 0; nf < 8; ++nf)
                    mma_f16(acc[mf][nf], ah[mf], &bf[nf * 2]);
        }
    }

    const int erow0 = bm + wm + (lid >> 2);
    const int ecol0 = bn + wn + (lid & 3) * 2;
#pragma unroll
    for (int mf = 0; mf < 2; ++mf)
#pragma unroll
        for (int nf = 0; nf < 8; ++nf)
#pragma unroll
            for (int half = 0; half < 2; ++half) {
                const int row = erow0 + mf * 16 + half * 8;
                const int col = ecol0 + nf * 8;
                if (col >= N) continue;
                float v0 = acc[mf][nf][half * 2 + 0];
                float v1 = acc[mf][nf][half * 2 + 1];
                if (mode == 0) {
                    *(float2*)(C + (size_t)row * ldc + col) = make_float2(v0, v1);
                } else if (mode == 1) {
                    const float2 rr = *(const float2*)(res1 + (size_t)row * ldr1 + col);
                    *(float2*)(C + (size_t)row * ldc + col) = make_float2(v0 + rr.x, v1 + rr.y);
                } else if (mode == 2) {
                    const float2 bb = *(const float2*)(bias + col);
                    v0 = fmaxf(v0 + bb.x, 0.f);
                    v1 = fmaxf(v1 + bb.y, 0.f);
                    *(__half2*)(Oh + (size_t)row * ldc + col) =
                        __half2(__float2half_rn(v0), __float2half_rn(v1));
                } else {
                    const float2 bb = *(const float2*)(bias + col);
                    const float2 r1 = *(const float2*)(res1 + (size_t)row * ldr1 + col);
                    const float2 r2 = *(const float2*)(res2 + (size_t)row * ldr2 + col);
                    *(float2*)(C + (size_t)row * ldc + col) =
                        make_float2(v0 + bb.x + r1.x + r2.x, v1 + bb.y + r1.y + r2.y);
                }
            }
}

// ------------------------------------------------------------------
// LayerNorm (D=1024): optional fp32 out + fp16 out
// ------------------------------------------------------------------
__global__ void ln_kernel(const float* __restrict__ x, const float* __restrict__ g,
                          const float* __restrict__ b, float* __restrict__ outf,
                          __half* __restrict__ oh) {
    __shared__ float rs[8], rq[8];
    const int tid = threadIdx.x;
    const size_t base = (size_t)blockIdx.x * DMODEL;
    float4 xv = *(const float4*)(x + base + tid * 4);
    float s = xv.x + xv.y + xv.z + xv.w;
    float q = xv.x * xv.x + xv.y * xv.y + xv.z * xv.z + xv.w * xv.w;
#pragma unroll
    for (int o = 16; o > 0; o >>= 1) {
        s += __shfl_xor_sync(0xffffffffu, s, o);
        q += __shfl_xor_sync(0xffffffffu, q, o);
    }
    if ((tid & 31) == 0) { rs[tid >> 5] = s; rq[tid >> 5] = q; }
    __syncthreads();
    s = rs[0] + rs[1] + rs[2] + rs[3] + rs[4] + rs[5] + rs[6] + rs[7];
    q = rq[0] + rq[1] + rq[2] + rq[3] + rq[4] + rq[5] + rq[6] + rq[7];
    const float mu = s * (1.0f / DMODEL);
    const float var = q * (1.0f / DMODEL) - mu * mu;
    const float rstd = rsqrtf(var + 1e-5f);
    float4 gv = *(const float4*)(g + tid * 4);
    float4 bv = *(const float4*)(b + tid * 4);
    float o0 = (xv.x - mu) * rstd * gv.x + bv.x;
    float o1 = (xv.y - mu) * rstd * gv.y + bv.y;
    float o2 = (xv.z - mu) * rstd * gv.z + bv.z;
    float o3 = (xv.w - mu) * rstd * gv.w + bv.w;
    if (outf) *(float4*)(outf + base + tid * 4) = make_float4(o0, o1, o2, o3);
    __half2* ph = (__half2*)(oh + base + tid * 4);
    ph[0] = __half2(__float2half_rn(o0), __float2half_rn(o1));
    ph[1] = __half2(__float2half_rn(o2), __float2half_rn(o3));
}

// ------------------------------------------------------------------
// weight fp32 -> fp16, vectorized (4 elems/thread)
// ------------------------------------------------------------------
__global__ void cvt_h(const float4* __restrict__ src, __half2* __restrict__ h, int n4) {
    const int i = blockIdx.x * blockDim.x + threadIdx.x;
    if (i < n4) {
        const float4 v = src[i];
        h[2 * i + 0] = __half2(__float2half_rn(v.x), __float2half_rn(v.y));
        h[2 * i + 1] = __half2(__float2half_rn(v.z), __float2half_rn(v.w));
    }
}

// ------------------------------------------------------------------
// causal depthwise conv + SiLU -> xc fp32 + fp16
// ------------------------------------------------------------------
__global__ void conv_silu_kernel(const float* __restrict__ conv_w, const float* __restrict__ conv_b) {
    const int idx = blockIdx.x * blockDim.x + threadIdx.x;
    const int d = idx & (DI - 1);
    const int t = idx >> 11;
    float acc = conv_b[d];
#pragma unroll
    for (int k = 0; k < 4; ++k) {
        const int tt = t + k - 3;
        if (tt >= 0) acc = fmaf(g_xz[(size_t)tt * (2 * DI) + d], conv_w[d * 4 + k], acc);
    }
    const float v = acc / (1.0f + __expf(-acc));
    g_xc[idx] = v;
    g_xc_h[idx] = __float2half_rn(v);
}

// ------------------------------------------------------------------
// pack (B, C) from proj
// ------------------------------------------------------------------
__global__ void pack_bc_kernel() {
    const int i = blockIdx.x * blockDim.x + threadIdx.x;   // L*16
    const int t = i >> 4, s = i & 15;
    g_bc[i] = make_float2(g_proj[t * NPROJ + DTRANK + s],
                          g_proj[t * NPROJ + DTRANK + DSTATE + s]);
}

// ------------------------------------------------------------------
// delta GEMM (SIMT, K=64): dx = (softplus(dt @ Wdt^T + b), delta*xc)
// ------------------------------------------------------------------
__global__ __launch_bounds__(256, 2)
void delta_gemm(const float* __restrict__ P, const float* __restrict__ W,
                const float* __restrict__ bias) {
    __shared__ float As[8][128];
    __shared__ float Bs[8][128];
    const int tid = threadIdx.x;
    const int bm = blockIdx.y * 128;
    const int bn = blockIdx.x * 128;
    const int aRow = tid >> 1, aCol = (tid & 1) * 4;
    const int tx = tid & 15, ty = tid >> 4;
    float acc[8][8];
#pragma unroll
    for (int i = 0; i < 8; ++i)
#pragma unroll
        for (int j = 0; j < 8; ++j) acc[i][j] = 0.0f;
    for (int k0 = 0; k0 < 64; k0 += 8) {
        float4 av = *(const float4*)(P + (size_t)(bm + aRow) * NPROJ + k0 + aCol);
        float4 bv = *(const float4*)(W + (size_t)(bn + aRow) * 64 + k0 + aCol);
        __syncthreads();
        As[aCol + 0][aRow] = av.x; As[aCol + 1][aRow] = av.y;
        As[aCol + 2][aRow] = av.z; As[aCol + 3][aRow] = av.w;
        Bs[aCol + 0][aRow] = bv.x; Bs[aCol + 1][aRow] = bv.y;
        Bs[aCol + 2][aRow] = bv.z; Bs[aCol + 3][aRow] = bv.w;
        __syncthreads();
#pragma unroll
        for (int kk = 0; kk < 8; ++kk) {
            float rm[8], rn[8];
            *(float4*)&rm[0] = *(const float4*)&As[kk][ty * 8];
            *(float4*)&rm[4] = *(const float4*)&As[kk][ty * 8 + 4];
            *(float4*)&rn[0] = *(const float4*)&Bs[kk][tx * 8];
            *(float4*)&rn[4] = *(const float4*)&Bs[kk][tx * 8 + 4];
#pragma unroll
            for (int i = 0; i < 8; ++i)
#pragma unroll
                for (int j = 0; j < 8; ++j) acc[i][j] = fmaf(rm[i], rn[j], acc[i][j]);
        }
    }
#pragma unroll
    for (int i = 0; i < 8; ++i) {
        const int row = bm + ty * 8 + i;
#pragma unroll
        for (int j = 0; j < 8; ++j) {
            const int col = bn + tx * 8 + j;
            float v = acc[i][j] + bias[col];
            v = fmaxf(v, 0.0f) + log1pf(__expf(-fabsf(v)));
            const float xcv = g_xc[(size_t)row * DI + col];
            g_dx[(size_t)row * DI + col] = make_float2(v, v * xcv);
        }
    }
}

// ------------------------------------------------------------------
// selective scan: 16 lanes per channel, one state per lane
// ------------------------------------------------------------------
__global__ void scan_kernel(const float* __restrict__ A_log) {
    const int s = threadIdx.x & 15;
    const int d = blockIdx.x * 16 + (threadIdx.x >> 4);
    const float a = -__expf(A_log[d * DSTATE + s]);
    float h = 0.0f;
    constexpr int PF = 8;
    float2 pd[PF], pb[PF];
#pragma unroll
    for (int i = 0; i < PF; ++i) {
        pd[i] = g_dx[(size_t)i * DI + d];
        pb[i] = g_bc[i * DSTATE + s];
    }
#pragma unroll 4
    for (int t = 0; t < LSEQ; ++t) {
        const int sl = t & (PF - 1);
        const float2 dxv = pd[sl];
        const float2 bcv = pb[sl];
        const int tp = t + PF;
        if (tp < LSEQ) {
            pd[sl] = g_dx[(size_t)tp * DI + d];
            pb[sl] = g_bc[tp * DSTATE + s];
        }
        const float dA = __expf(a * dxv.x);
        h = fmaf(h, dA, dxv.y * bcv.x);
        float p = h * bcv.y;
        p += __shfl_xor_sync(0xffffffffu, p, 1);
        p += __shfl_xor_sync(0xffffffffu, p, 2);
        p += __shfl_xor_sync(0xffffffffu, p, 4);
        p += __shfl_xor_sync(0xffffffffu, p, 8);
        if (s == 0) g_ys[(size_t)t * DI + d] = p;
    }
}

// ------------------------------------------------------------------
// y = (ys + xc*Dp) * silu(z) -> fp16
// ------------------------------------------------------------------
__global__ void ygate_kernel(const float* __restrict__ Dp) {
    const int idx = blockIdx.x * blockDim.x + threadIdx.x;
    const int d = idx & (DI - 1);
    const int t = idx >> 11;
    const float z = g_xz[(size_t)t * (2 * DI) + DI + d];
    const float sig = 1.0f / (1.0f + __expf(-z));
    const float v = fmaf(g_xc[idx], Dp[d], g_ys[idx]) * (z * sig);
    g_y_h[idx] = __float2half_rn(v);
}

// ------------------------------------------------------------------
// launch
// ------------------------------------------------------------------
extern "C" void kernel_launch(void* const* d_in, const int* in_sizes, int n_in,
                              void* d_out, int out_size) {
    const float* x         = (const float*)d_in[0];
    const float* ln1_g     = (const float*)d_in[1];
    const float* ln1_b     = (const float*)d_in[2];
    const float* ln2_g     = (const float*)d_in[3];
    const float* ln2_b     = (const float*)d_in[4];
    const float* in_proj_w = (const float*)d_in[5];
    const float* conv_w    = (const float*)d_in[6];
    const float* conv_b    = (const float*)d_in[7];
    const float* x_proj_w  = (const float*)d_in[8];
    const float* dt_proj_w = (const float*)d_in[9];
    const float* dt_proj_b = (const float*)d_in[10];
    const float* A_log     = (const float*)d_in[11];
    const float* D_param   = (const float*)d_in[12];
    const float* out_proj_w= (const float*)d_in[13];
    const float* ffn_w1    = (const float*)d_in[14];
    const float* ffn_b1    = (const float*)d_in[15];
    const float* ffn_w2    = (const float*)d_in[16];
    const float* ffn_b2    = (const float*)d_in[17];
    float* out = (float*)d_out;

    cudaFuncSetAttribute(tc_gemm, cudaFuncAttributeMaxDynamicSharedMemorySize, SM_GEMM_TOTAL);

#define SYM(p, s) void* p; cudaGetSymbolAddress(&p, s)
    SYM(p_xz, g_xz); SYM(p_xc, g_xc); SYM(p_proj, g_proj); SYM(p_h, g_h); SYM(p_n, g_n);
    SYM(p_hln_h, g_hln_h);
    SYM(p_xc_h, g_xc_h);
    SYM(p_y_h, g_y_h);
    SYM(p_n_h, g_n_h);
    SYM(p_f1_h, g_f1_h);
    SYM(p_win_h, g_win_h);
    SYM(p_wxp_h, g_wxp_h);
    SYM(p_wout_h, g_wout_h);
    SYM(p_wf1_h, g_wf1_h);
    SYM(p_wf2_h, g_wf2_h);
#undef SYM

    // weight conversions (vectorized x4)
    cvt_h<<<(2 * DI * DMODEL / 4 + 255) / 256, 256>>>((const float4*)in_proj_w, (__half2*)p_win_h, 2 * DI * DMODEL / 4);
    cvt_h<<<(NPROJ * DI / 4 + 255) / 256, 256>>>((const float4*)x_proj_w, (__half2*)p_wxp_h, NPROJ * DI / 4);
    cvt_h<<<(DMODEL * DI / 4 + 255) / 256, 256>>>((const float4*)out_proj_w, (__half2*)p_wout_h, DMODEL * DI / 4);
    cvt_h<<<(HIDF * DMODEL / 4 + 255) / 256, 256>>>((const float4*)ffn_w1, (__half2*)p_wf1_h, HIDF * DMODEL / 4);
    cvt_h<<<(DMODEL * HIDF / 4 + 255) / 256, 256>>>((const float4*)ffn_w2, (__half2*)p_wf2_h, DMODEL * HIDF / 4);

    // 1) LN1 -> hln fp16
    ln_kernel<<<LSEQ, 256>>>(x, ln1_g, ln1_b, nullptr, (__half*)p_hln_h);

    // 2) xz = hln @ in_proj_w^T   [2048, 4096]
    tc_gemm<<<dim3(32, 16), 256, SM_GEMM_TOTAL>>>(
        (__half*)p_hln_h, (__half*)p_win_h,
        (float*)p_xz, nullptr, 2 * DI, 2 * DI, DMODEL, 0,
        nullptr, nullptr, 0, nullptr, 0);

    // 3) conv + silu -> xc (fp32 + fp16)
    conv_silu_kernel<<<(LSEQ * DI) / 256, 256>>>(conv_w, conv_b);

    // 4) proj = xc @ x_proj_w^T   [2048, 96]
    tc_gemm<<<dim3(1, 16), 256, SM_GEMM_TOTAL>>>(
        (__half*)p_xc_h, (__half*)p_wxp_h,
        (float*)p_proj, nullptr, NPROJ, NPROJ, DI, 0,
        nullptr, nullptr, 0, nullptr, 0);

    // 5) pack (B, C)
    pack_bc_kernel<<<(LSEQ * DSTATE) / 256, 256>>>();

    // 6) delta = softplus(dt @ dt_proj_w^T + b); dx = (delta, delta*xc)
    delta_gemm<<<dim3(DI / 128, LSEQ / 128), 256>>>((const float*)p_proj, dt_proj_w, dt_proj_b);

    // 7) selective scan
    scan_kernel<<<DI / 16, 256>>>(A_log);

    // 8) y gate -> y fp16
    ygate_kernel<<<(LSEQ * DI) / 256, 256>>>(D_param);

    // 9) h = y @ out_proj_w^T + x   [2048, 1024]
    tc_gemm<<<dim3(8, 16), 256, SM_GEMM_TOTAL>>>(
        (__half*)p_y_h, (__half*)p_wout_h,
        (float*)p_h, nullptr, DMODEL, DMODEL, DI, 1,
        nullptr, x, DMODEL, nullptr, 0);

    // 10) LN2 -> n (fp32 + fp16)
    ln_kernel<<<LSEQ, 256>>>((const float*)p_h, ln2_g, ln2_b, (float*)p_n, (__half*)p_n_h);

    // 11) f1 = relu(n @ ffn_w1^T + b1) -> fp16   [2048, 4096]
    tc_gemm<<<dim3(32, 16), 256, SM_GEMM_TOTAL>>>(
        (__half*)p_n_h, (__half*)p_wf1_h,
        nullptr, (__half*)p_f1_h, HIDF, HIDF, DMODEL, 2,
        ffn_b1, nullptr, 0, nullptr, 0);

    // 12) out = f1 @ ffn_w2^T + b2 + n + h   [2048, 1024]
    tc_gemm<<<dim3(8, 16), 256, SM_GEMM_TOTAL>>>(
        (__half*)p_f1_h, (__half*)p_wf2_h,
        out, nullptr, DMODEL, DMODEL, HIDF, 3,
        ffn_b2, (const float*)p_n, DMODEL, (const float*)p_h, DMODEL);
}

// round 7
// speedup vs baseline: 2.5679x; 1.0470x over previous
#include <cuda_runtime.h>
#include <cuda_fp16.h>
#include <cstdint>
#include <cstddef>

#define LSEQ 2048
#define DMODEL 1024
#define DI 2048
#define DSTATE 16
#define DTRANK 64
#define HIDF 4096
#define NPROJ 96

// ------------------------------------------------------------------
// scratch (device globals; no allocation allowed)
// ------------------------------------------------------------------
__device__ float  g_xz[LSEQ * 2 * DI];
__device__ float  g_xc[LSEQ * DI];
__device__ float  g_proj[LSEQ * NPROJ];
__device__ float2 g_dx[LSEQ * DI];          // (delta, delta*xc)
__device__ float2 g_bc[LSEQ * DSTATE];      // (B, C)
__device__ float  g_ys[LSEQ * DI];
__device__ float  g_h[LSEQ * DMODEL];
__device__ float  g_n[LSEQ * DMODEL];

// fp16 activations, TILE-PACKED layout (128x64 swizzled tiles)
__device__ __half g_hln_h[LSEQ * DMODEL];
__device__ __half g_xc_h[LSEQ * DI];
__device__ __half g_y_h[LSEQ * DI];
__device__ __half g_n_h[LSEQ * DMODEL];
__device__ __half g_f1_h[LSEQ * HIDF];

// fp16 weights, TILE-PACKED (rows padded to multiple of 128)
__device__ __half g_win_h[2 * DI * DMODEL];
__device__ __half g_wxp_h[128 * DI];
__device__ __half g_wout_h[DMODEL * DI];
__device__ __half g_wf1_h[HIDF * DMODEL];
__device__ __half g_wf2_h[DMODEL * HIDF];

// ------------------------------------------------------------------
// packed-tile addressing: element (row, col) of a [R x ldk] fp16 matrix
// tile (row/128, col/64) is 8192 halves, contiguous; within tile the
// 16B quads are SW128-swizzled so a raw byte copy into smem is
// directly consumable by ldmatrix with sw128 addressing.
// ------------------------------------------------------------------
__device__ __forceinline__ size_t pk(int row, int col, int ldk) {
    size_t t = (size_t)(row >> 7) * (ldk >> 6) + (col >> 6);
    const int r = row & 127;
    return t * 8192 + r * 64 + ((((col >> 3) & 7) ^ (r & 7)) << 3) + (col & 7);
}

// ------------------------------------------------------------------
// PTX helpers
// ------------------------------------------------------------------
__device__ __forceinline__ uint32_t smem_u32(const void* p) {
    uint32_t a;
    asm("{ .reg .u64 t; cvta.to.shared.u64 t, %1; cvt.u32.u64 %0, t; }" : "=r"(a) : "l"(p));
    return a;
}
__device__ __forceinline__ void mbar_init(uint32_t a, uint32_t cnt) {
    asm volatile("mbarrier.init.shared.b64 [%0], %1;" :: "r"(a), "r"(cnt) : "memory");
}
__device__ __forceinline__ void mbar_expect_tx(uint32_t a, uint32_t bytes) {
    asm volatile("mbarrier.arrive.expect_tx.shared.b64 _, [%0], %1;"
                 :: "r"(a), "r"(bytes) : "memory");
}
__device__ __forceinline__ void mbar_wait(uint32_t a, uint32_t parity) {
    asm volatile(
        "{\n\t.reg .pred P;\n\t"
        "WL_%=:\n\t"
        "mbarrier.try_wait.parity.acquire.cta.shared::cta.b64 P, [%0], %1, 0x989680;\n\t"
        "@P bra.uni WD_%=;\n\t"
        "bra.uni WL_%=;\n\t"
        "WD_%=:\n\t}"
        :: "r"(a), "r"(parity) : "memory");
}
__device__ __forceinline__ void bulk_g2s(uint32_t dst, const void* src, uint32_t bytes, uint32_t mbar) {
    asm volatile(
        "cp.async.bulk.shared::cta.global.mbarrier::complete_tx::bytes [%0], [%1], %2, [%3];"
        :: "r"(dst), "l"(src), "r"(bytes), "r"(mbar) : "memory");
}
__device__ __forceinline__ void ldsm_x4(uint32_t addr, uint32_t* r) {
    asm volatile("ldmatrix.sync.aligned.m8n8.x4.shared.b16 {%0,%1,%2,%3}, [%4];"
                 : "=r"(r[0]), "=r"(r[1]), "=r"(r[2]), "=r"(r[3]) : "r"(addr));
}
__device__ __forceinline__ void mma_f16(float* c, const uint32_t* a, const uint32_t* b) {
    asm volatile(
        "mma.sync.aligned.m16n8k16.row.col.f32.f16.f16.f32 "
        "{%0,%1,%2,%3}, {%4,%5,%6,%7}, {%8,%9}, {%0,%1,%2,%3};"
        : "+f"(c[0]), "+f"(c[1]), "+f"(c[2]), "+f"(c[3])
        : "r"(a[0]), "r"(a[1]), "r"(a[2]), "r"(a[3]), "r"(b[0]), "r"(b[1]));
}
__device__ __forceinline__ uint32_t sw128(uint32_t bo) { return bo ^ ((bo >> 3) & 0x70); }

// ------------------------------------------------------------------
// GEMM: C[M,N] = A[M,K] @ W[N,K]^T, packed fp16 operands, fp32 accum.
// BMxBN(128) tile, k-chunk 64, 3-stage bulk-copy ring (2 UBLKCP/chunk).
// modes: 0 store f32 | 1 +res1 f32 | 2 bias+relu -> packed fp16 | 3 bias+res1+res2 f32
// ------------------------------------------------------------------
template<int BM>
__global__ __launch_bounds__(256, 2)
void tc_gemm(const __half* __restrict__ Apk, const __half* __restrict__ Bpk,
             float* __restrict__ C, __half* __restrict__ Oh,
             int ldc, int N, int K, int mode,
             const float* __restrict__ bias,
             const float* __restrict__ res1, int ldr1,
             const float* __restrict__ res2, int ldr2) {
    constexpr int NF = (BM == 128) ? 8 : 4;       // 8-col n-frags per warp
    constexpr int ABYTES = BM * 128;
    constexpr int STB = ABYTES + 16384;           // stage bytes (A + B tile)
    extern __shared__ char smem[];
    const uint32_t sb = smem_u32(smem);           // 3 mbarriers at sb+0/8/16
    const uint32_t tiles = sb + 1024;
    const int tid = threadIdx.x;
    const int wid = tid >> 5, lid = tid & 31;
    const int bm = blockIdx.y * BM;
    const int bn = blockIdx.x * 128;
    const int wm = (BM == 128) ? (wid & 3) * 32 : (wid & 1) * 32;
    const int wn = (BM == 128) ? (wid >> 2) * 64 : (wid >> 1) * 32;
    const int nch = K >> 6;
    const size_t aBase = (size_t)(bm >> 7) * nch * 8192 + (size_t)((bm >> 6) & 1) * 4096;
    const size_t bBase = (size_t)(bn >> 7) * nch * 8192;

    if (tid == 0) {
        mbar_init(sb + 0, 1); mbar_init(sb + 8, 1); mbar_init(sb + 16, 1);
        asm volatile("fence.proxy.async.shared::cta;" ::: "memory");
    }
    __syncthreads();

    float acc[2][NF][4];
#pragma unroll
    for (int mf = 0; mf < 2; ++mf)
#pragma unroll
        for (int nf = 0; nf < NF; ++nf)
#pragma unroll
            for (int v = 0; v < 4; ++v) acc[mf][nf][v] = 0.0f;

    const int mat = lid >> 3;
    const int lrow = lid & 7;
    const int rowA = wm + (mat & 1) * 8 + lrow;
    const int kqA = (mat >> 1);
    const int rowB = wn + (mat >> 1) * 8 + lrow;
    const int kqB = (mat & 1);

    if (tid == 0) {
#pragma unroll
        for (int c = 0; c < 2; ++c) {
            const uint32_t mb = sb + c * 8;
            const uint32_t dst = tiles + c * STB;
            mbar_expect_tx(mb, STB);
            bulk_g2s(dst, Apk + aBase + (size_t)c * 8192, ABYTES, mb);
            bulk_g2s(dst + ABYTES, Bpk + bBase + (size_t)c * 8192, 16384, mb);
        }
    }

    for (int c = 0; c < nch; ++c) {
        if (tid == 0 && c + 2 < nch) {
            const int s = (c + 2) % 3;
            const uint32_t mb = sb + s * 8;
            const uint32_t dst = tiles + s * STB;
            mbar_expect_tx(mb, STB);
            bulk_g2s(dst, Apk + aBase + (size_t)(c + 2) * 8192, ABYTES, mb);
            bulk_g2s(dst + ABYTES, Bpk + bBase + (size_t)(c + 2) * 8192, 16384, mb);
        }
        mbar_wait(sb + (c % 3) * 8, (uint32_t)((c / 3) & 1));

        const uint32_t base = tiles + (c % 3) * STB;
#pragma unroll
        for (int ks = 0; ks < 4; ++ks) {
            uint32_t ah[2][4], bf[NF * 2];
#pragma unroll
            for (int mf = 0; mf < 2; ++mf) {
                const uint32_t bo = (uint32_t)(rowA + mf * 16) * 128 + ks * 32 + kqA * 16;
                ldsm_x4(base + sw128(bo), ah[mf]);
            }
#pragma unroll
            for (int p = 0; p < NF / 2; ++p) {
                const uint32_t bo = (uint32_t)(rowB + p * 16) * 128 + ks * 32 + kqB * 16;
                ldsm_x4(base + ABYTES + sw128(bo), &bf[p * 4]);
            }
#pragma unroll
            for (int mf = 0; mf < 2; ++mf)
#pragma unroll
                for (int nf = 0; nf < NF; ++nf)
                    mma_f16(acc[mf][nf], ah[mf], &bf[nf * 2]);
        }
        __syncthreads();
    }

    const int erow0 = bm + wm + (lid >> 2);
    const int ecol0 = bn + wn + (lid & 3) * 2;
#pragma unroll
    for (int mf = 0; mf < 2; ++mf)
#pragma unroll
        for (int nf = 0; nf < NF; ++nf)
#pragma unroll
            for (int half = 0; half < 2; ++half) {
                const int row = erow0 + mf * 16 + half * 8;
                const int col = ecol0 + nf * 8;
                if (col >= N) continue;
                float v0 = acc[mf][nf][half * 2 + 0];
                float v1 = acc[mf][nf][half * 2 + 1];
                if (mode == 0) {
                    *(float2*)(C + (size_t)row * ldc + col) = make_float2(v0, v1);
                } else if (mode == 1) {
                    const float2 rr = *(const float2*)(res1 + (size_t)row * ldr1 + col);
                    *(float2*)(C + (size_t)row * ldc + col) = make_float2(v0 + rr.x, v1 + rr.y);
                } else if (mode == 2) {
                    const float2 bb = *(const float2*)(bias + col);
                    v0 = fmaxf(v0 + bb.x, 0.f);
                    v1 = fmaxf(v1 + bb.y, 0.f);
                    *(__half2*)(Oh + pk(row, col, ldc)) =
                        __half2(__float2half_rn(v0), __float2half_rn(v1));
                } else {
                    const float2 bb = *(const float2*)(bias + col);
                    const float2 r1 = *(const float2*)(res1 + (size_t)row * ldr1 + col);
                    const float2 r2 = *(const float2*)(res2 + (size_t)row * ldr2 + col);
                    *(float2*)(C + (size_t)row * ldc + col) =
                        make_float2(v0 + bb.x + r1.x + r2.x, v1 + bb.y + r1.y + r2.y);
                }
            }
}

// ------------------------------------------------------------------
// LayerNorm (D=1024): optional fp32 out + packed fp16 out
// ------------------------------------------------------------------
__global__ void ln_kernel(const float* __restrict__ x, const float* __restrict__ g,
                          const float* __restrict__ b, float* __restrict__ outf,
                          __half* __restrict__ oh) {
    __shared__ float rs[8], rq[8];
    const int tid = threadIdx.x;
    const size_t base = (size_t)blockIdx.x * DMODEL;
    float4 xv = *(const float4*)(x + base + tid * 4);
    float s = xv.x + xv.y + xv.z + xv.w;
    float q = xv.x * xv.x + xv.y * xv.y + xv.z * xv.z + xv.w * xv.w;
#pragma unroll
    for (int o = 16; o > 0; o >>= 1) {
        s += __shfl_xor_sync(0xffffffffu, s, o);
        q += __shfl_xor_sync(0xffffffffu, q, o);
    }
    if ((tid & 31) == 0) { rs[tid >> 5] = s; rq[tid >> 5] = q; }
    __syncthreads();
    s = rs[0] + rs[1] + rs[2] + rs[3] + rs[4] + rs[5] + rs[6] + rs[7];
    q = rq[0] + rq[1] + rq[2] + rq[3] + rq[4] + rq[5] + rq[6] + rq[7];
    const float mu = s * (1.0f / DMODEL);
    const float var = q * (1.0f / DMODEL) - mu * mu;
    const float rstd = rsqrtf(var + 1e-5f);
    float4 gv = *(const float4*)(g + tid * 4);
    float4 bv = *(const float4*)(b + tid * 4);
    float o0 = (xv.x - mu) * rstd * gv.x + bv.x;
    float o1 = (xv.y - mu) * rstd * gv.y + bv.y;
    float o2 = (xv.z - mu) * rstd * gv.z + bv.z;
    float o3 = (xv.w - mu) * rstd * gv.w + bv.w;
    if (outf) *(float4*)(outf + base + tid * 4) = make_float4(o0, o1, o2, o3);
    const int col = tid * 4;
    __half2* ph = (__half2*)(oh + pk(blockIdx.x, col, DMODEL));
    ph[0] = __half2(__float2half_rn(o0), __float2half_rn(o1));
    ph[1] = __half2(__float2half_rn(o2), __float2half_rn(o3));
}

// ------------------------------------------------------------------
// weight fp32 -> packed fp16 (4 elems/thread)
// ------------------------------------------------------------------
__global__ void cvt_h(const float4* __restrict__ src, __half* __restrict__ dst,
                      int n4, int kshift) {
    const int i = blockIdx.x * blockDim.x + threadIdx.x;
    if (i < n4) {
        const float4 v = src[i];
        const int e = i << 2;
        const int row = e >> kshift;
        const int col = e & ((1 << kshift) - 1);
        __half2* p = (__half2*)(dst + pk(row, col, 1 << kshift));
        p[0] = __half2(__float2half_rn(v.x), __float2half_rn(v.y));
        p[1] = __half2(__float2half_rn(v.z), __float2half_rn(v.w));
    }
}

// ------------------------------------------------------------------
// causal depthwise conv + SiLU -> xc fp32 + packed fp16
// ------------------------------------------------------------------
__global__ void conv_silu_kernel(const float* __restrict__ conv_w, const float* __restrict__ conv_b) {
    const int idx = blockIdx.x * blockDim.x + threadIdx.x;
    const int d = idx & (DI - 1);
    const int t = idx >> 11;
    float acc = conv_b[d];
#pragma unroll
    for (int k = 0; k < 4; ++k) {
        const int tt = t + k - 3;
        if (tt >= 0) acc = fmaf(g_xz[(size_t)tt * (2 * DI) + d], conv_w[d * 4 + k], acc);
    }
    const float v = acc / (1.0f + __expf(-acc));
    g_xc[idx] = v;
    g_xc_h[pk(t, d, DI)] = __float2half_rn(v);
}

// ------------------------------------------------------------------
// pack (B, C) from proj
// ------------------------------------------------------------------
__global__ void pack_bc_kernel() {
    const int i = blockIdx.x * blockDim.x + threadIdx.x;   // L*16
    const int t = i >> 4, s = i & 15;
    g_bc[i] = make_float2(g_proj[t * NPROJ + DTRANK + s],
                          g_proj[t * NPROJ + DTRANK + DSTATE + s]);
}

// ------------------------------------------------------------------
// delta GEMM (SIMT, K=64): dx = (softplus(dt @ Wdt^T + b), delta*xc)
// ------------------------------------------------------------------
__global__ __launch_bounds__(256, 2)
void delta_gemm(const float* __restrict__ P, const float* __restrict__ W,
                const float* __restrict__ bias) {
    __shared__ float As[8][128];
    __shared__ float Bs[8][128];
    const int tid = threadIdx.x;
    const int bm = blockIdx.y * 128;
    const int bn = blockIdx.x * 128;
    const int aRow = tid >> 1, aCol = (tid & 1) * 4;
    const int tx = tid & 15, ty = tid >> 4;
    float acc[8][8];
#pragma unroll
    for (int i = 0; i < 8; ++i)
#pragma unroll
        for (int j = 0; j < 8; ++j) acc[i][j] = 0.0f;
    for (int k0 = 0; k0 < 64; k0 += 8) {
        float4 av = *(const float4*)(P + (size_t)(bm + aRow) * NPROJ + k0 + aCol);
        float4 bv = *(const float4*)(W + (size_t)(bn + aRow) * 64 + k0 + aCol);
        __syncthreads();
        As[aCol + 0][aRow] = av.x; As[aCol + 1][aRow] = av.y;
        As[aCol + 2][aRow] = av.z; As[aCol + 3][aRow] = av.w;
        Bs[aCol + 0][aRow] = bv.x; Bs[aCol + 1][aRow] = bv.y;
        Bs[aCol + 2][aRow] = bv.z; Bs[aCol + 3][aRow] = bv.w;
        __syncthreads();
#pragma unroll
        for (int kk = 0; kk < 8; ++kk) {
            float rm[8], rn[8];
            *(float4*)&rm[0] = *(const float4*)&As[kk][ty * 8];
            *(float4*)&rm[4] = *(const float4*)&As[kk][ty * 8 + 4];
            *(float4*)&rn[0] = *(const float4*)&Bs[kk][tx * 8];
            *(float4*)&rn[4] = *(const float4*)&Bs[kk][tx * 8 + 4];
#pragma unroll
            for (int i = 0; i < 8; ++i)
#pragma unroll
                for (int j = 0; j < 8; ++j) acc[i][j] = fmaf(rm[i], rn[j], acc[i][j]);
        }
    }
#pragma unroll
    for (int i = 0; i < 8; ++i) {
        const int row = bm + ty * 8 + i;
#pragma unroll
        for (int j = 0; j < 8; ++j) {
            const int col = bn + tx * 8 + j;
            float v = acc[i][j] + bias[col];
            v = fmaxf(v, 0.0f) + log1pf(__expf(-fabsf(v)));
            const float xcv = g_xc[(size_t)row * DI + col];
            g_dx[(size_t)row * DI + col] = make_float2(v, v * xcv);
        }
    }
}

// ------------------------------------------------------------------
// selective scan: 16 lanes per channel, one state per lane
// ------------------------------------------------------------------
__global__ void scan_kernel(const float* __restrict__ A_log) {
    const int s = threadIdx.x & 15;
    const int d = blockIdx.x * 16 + (threadIdx.x >> 4);
    const float a = -__expf(A_log[d * DSTATE + s]);
    float h = 0.0f;
    constexpr int PF = 8;
    float2 pd[PF], pb[PF];
#pragma unroll
    for (int i = 0; i < PF; ++i) {
        pd[i] = g_dx[(size_t)i * DI + d];
        pb[i] = g_bc[i * DSTATE + s];
    }
#pragma unroll 4
    for (int t = 0; t < LSEQ; ++t) {
        const int sl = t & (PF - 1);
        const float2 dxv = pd[sl];
        const float2 bcv = pb[sl];
        const int tp = t + PF;
        if (tp < LSEQ) {
            pd[sl] = g_dx[(size_t)tp * DI + d];
            pb[sl] = g_bc[tp * DSTATE + s];
        }
        const float dA = __expf(a * dxv.x);
        h = fmaf(h, dA, dxv.y * bcv.x);
        float p = h * bcv.y;
        p += __shfl_xor_sync(0xffffffffu, p, 1);
        p += __shfl_xor_sync(0xffffffffu, p, 2);
        p += __shfl_xor_sync(0xffffffffu, p, 4);
        p += __shfl_xor_sync(0xffffffffu, p, 8);
        if (s == 0) g_ys[(size_t)t * DI + d] = p;
    }
}

// ------------------------------------------------------------------
// y = (ys + xc*Dp) * silu(z) -> packed fp16
// ------------------------------------------------------------------
__global__ void ygate_kernel(const float* __restrict__ Dp) {
    const int idx = blockIdx.x * blockDim.x + threadIdx.x;
    const int d = idx & (DI - 1);
    const int t = idx >> 11;
    const float z = g_xz[(size_t)t * (2 * DI) + DI + d];
    const float sig = 1.0f / (1.0f + __expf(-z));
    const float v = fmaf(g_xc[idx], Dp[d], g_ys[idx]) * (z * sig);
    g_y_h[pk(t, d, DI)] = __float2half_rn(v);
}

// ------------------------------------------------------------------
// launch
// ------------------------------------------------------------------
#define SMEM_BIG   (1024 + 3 * (128 * 128 + 16384))   // 99328
#define SMEM_SMALL (1024 + 3 * (64 * 128 + 16384))    // 74752

extern "C" void kernel_launch(void* const* d_in, const int* in_sizes, int n_in,
                              void* d_out, int out_size) {
    const float* x         = (const float*)d_in[0];
    const float* ln1_g     = (const float*)d_in[1];
    const float* ln1_b     = (const float*)d_in[2];
    const float* ln2_g     = (const float*)d_in[3];
    const float* ln2_b     = (const float*)d_in[4];
    const float* in_proj_w = (const float*)d_in[5];
    const float* conv_w    = (const float*)d_in[6];
    const float* conv_b    = (const float*)d_in[7];
    const float* x_proj_w  = (const float*)d_in[8];
    const float* dt_proj_w = (const float*)d_in[9];
    const float* dt_proj_b = (const float*)d_in[10];
    const float* A_log     = (const float*)d_in[11];
    const float* D_param   = (const float*)d_in[12];
    const float* out_proj_w= (const float*)d_in[13];
    const float* ffn_w1    = (const float*)d_in[14];
    const float* ffn_b1    = (const float*)d_in[15];
    const float* ffn_w2    = (const float*)d_in[16];
    const float* ffn_b2    = (const float*)d_in[17];
    float* out = (float*)d_out;

    cudaFuncSetAttribute(tc_gemm<128>, cudaFuncAttributeMaxDynamicSharedMemorySize, SMEM_BIG);
    cudaFuncSetAttribute(tc_gemm<64>,  cudaFuncAttributeMaxDynamicSharedMemorySize, SMEM_SMALL);

#define SYM(p, s) void* p; cudaGetSymbolAddress(&p, s)
    SYM(p_xz, g_xz); SYM(p_xc, g_xc); SYM(p_proj, g_proj); SYM(p_h, g_h); SYM(p_n, g_n);
    SYM(p_hln_h, g_hln_h);
    SYM(p_xc_h, g_xc_h);
    SYM(p_y_h, g_y_h);
    SYM(p_n_h, g_n_h);
    SYM(p_f1_h, g_f1_h);
    SYM(p_win_h, g_win_h);
    SYM(p_wxp_h, g_wxp_h);
    SYM(p_wout_h, g_wout_h);
    SYM(p_wf1_h, g_wf1_h);
    SYM(p_wf2_h, g_wf2_h);
#undef SYM

    // weight conversions into packed-tile layout
    cvt_h<<<(2 * DI * DMODEL / 4 + 255) / 256, 256>>>((const float4*)in_proj_w, (__half*)p_win_h, 2 * DI * DMODEL / 4, 10);
    cvt_h<<<(NPROJ * DI / 4 + 255) / 256, 256>>>((const float4*)x_proj_w, (__half*)p_wxp_h, NPROJ * DI / 4, 11);
    cvt_h<<<(DMODEL * DI / 4 + 255) / 256, 256>>>((const float4*)out_proj_w, (__half*)p_wout_h, DMODEL * DI / 4, 11);
    cvt_h<<<(HIDF * DMODEL / 4 + 255) / 256, 256>>>((const float4*)ffn_w1, (__half*)p_wf1_h, HIDF * DMODEL / 4, 10);
    cvt_h<<<(DMODEL * HIDF / 4 + 255) / 256, 256>>>((const float4*)ffn_w2, (__half*)p_wf2_h, DMODEL * HIDF / 4, 12);

    // 1) LN1 -> hln (packed fp16)
    ln_kernel<<<LSEQ, 256>>>(x, ln1_g, ln1_b, nullptr, (__half*)p_hln_h);

    // 2) xz = hln @ in_proj_w^T   [2048, 4096]
    tc_gemm<128><<<dim3(32, 16), 256, SMEM_BIG>>>(
        (__half*)p_hln_h, (__half*)p_win_h,
        (float*)p_xz, nullptr, 2 * DI, 2 * DI, DMODEL, 0,
        nullptr, nullptr, 0, nullptr, 0);

    // 3) conv + silu -> xc (fp32 + packed fp16)
    conv_silu_kernel<<<(LSEQ * DI) / 256, 256>>>(conv_w, conv_b);

    // 4) proj = xc @ x_proj_w^T   [2048, 96]
    tc_gemm<64><<<dim3(1, 32), 256, SMEM_SMALL>>>(
        (__half*)p_xc_h, (__half*)p_wxp_h,
        (float*)p_proj, nullptr, NPROJ, NPROJ, DI, 0,
        nullptr, nullptr, 0, nullptr, 0);

    // 5) pack (B, C)
    pack_bc_kernel<<<(LSEQ * DSTATE) / 256, 256>>>();

    // 6) delta = softplus(dt @ dt_proj_w^T + b); dx = (delta, delta*xc)
    delta_gemm<<<dim3(DI / 128, LSEQ / 128), 256>>>((const float*)p_proj, dt_proj_w, dt_proj_b);

    // 7) selective scan
    scan_kernel<<<DI / 16, 256>>>(A_log);

    // 8) y gate -> y (packed fp16)
    ygate_kernel<<<(LSEQ * DI) / 256, 256>>>(D_param);

    // 9) h = y @ out_proj_w^T + x   [2048, 1024]
    tc_gemm<64><<<dim3(8, 32), 256, SMEM_SMALL>>>(
        (__half*)p_y_h, (__half*)p_wout_h,
        (float*)p_h, nullptr, DMODEL, DMODEL, DI, 1,
        nullptr, x, DMODEL, nullptr, 0);

    // 10) LN2 -> n (fp32 + packed fp16)
    ln_kernel<<<LSEQ, 256>>>((const float*)p_h, ln2_g, ln2_b, (float*)p_n, (__half*)p_n_h);

    // 11) f1 = relu(n @ ffn_w1^T + b1) -> packed fp16   [2048, 4096]
    tc_gemm<128><<<dim3(32, 16), 256, SMEM_BIG>>>(
        (__half*)p_n_h, (__half*)p_wf1_h,
        nullptr, (__half*)p_f1_h, HIDF, HIDF, DMODEL, 2,
        ffn_b1, nullptr, 0, nullptr, 0);

    // 12) out = f1 @ ffn_w2^T + b2 + n + h   [2048, 1024]
    tc_gemm<64><<<dim3(8, 32), 256, SMEM_SMALL>>>(
        (__half*)p_f1_h, (__half*)p_wf2_h,
        out, nullptr, DMODEL, DMODEL, HIDF, 3,
        ffn_b2, (const float*)p_n, DMODEL, (const float*)p_h, DMODEL);
}

// round 8
// speedup vs baseline: 5.6328x; 2.1936x over previous
#include <cuda_runtime.h>
#include <cuda_fp16.h>
#include <cstdint>
#include <cstddef>

#define LSEQ 2048
#define DMODEL 1024
#define DI 2048
#define DSTATE 16
#define DTRANK 64
#define HIDF 4096
#define NPROJ 96

// ------------------------------------------------------------------
// scratch (device globals; no allocation allowed)
// ------------------------------------------------------------------
__device__ float  g_xz[LSEQ * 2 * DI];
__device__ float  g_xc[LSEQ * DI];
__device__ float  g_proj[LSEQ * NPROJ];
__device__ float2 g_dx[LSEQ * DI];          // (delta, delta*xc)
__device__ float2 g_bc[LSEQ * DSTATE];      // (B, C)
__device__ float  g_ys[LSEQ * DI];
__device__ float  g_h[LSEQ * DMODEL];
__device__ float  g_n[LSEQ * DMODEL];

// fp16 activations, TILE-PACKED layout (128x64 swizzled tiles)
__device__ __half g_hln_h[LSEQ * DMODEL];
__device__ __half g_xc_h[LSEQ * DI];
__device__ __half g_y_h[LSEQ * DI];
__device__ __half g_n_h[LSEQ * DMODEL];
__device__ __half g_f1_h[LSEQ * HIDF];

// fp16 weights, TILE-PACKED (rows padded to multiple of 128)
__device__ __half g_win_h[2 * DI * DMODEL];
__device__ __half g_wxp_h[128 * DI];
__device__ __half g_wout_h[DMODEL * DI];
__device__ __half g_wf1_h[HIDF * DMODEL];
__device__ __half g_wf2_h[DMODEL * HIDF];

// ------------------------------------------------------------------
// packed-tile addressing (128x64 fp16 tiles, SW128-swizzled quads)
// ------------------------------------------------------------------
__device__ __forceinline__ size_t pk(int row, int col, int ldk) {
    size_t t = (size_t)(row >> 7) * (ldk >> 6) + (col >> 6);
    const int r = row & 127;
    return t * 8192 + r * 64 + ((((col >> 3) & 7) ^ (r & 7)) << 3) + (col & 7);
}

// ------------------------------------------------------------------
// PTX helpers
// ------------------------------------------------------------------
__device__ __forceinline__ uint32_t smem_u32(const void* p) {
    uint32_t a;
    asm("{ .reg .u64 t; cvta.to.shared.u64 t, %1; cvt.u32.u64 %0, t; }" : "=r"(a) : "l"(p));
    return a;
}
__device__ __forceinline__ void mbar_init(uint32_t a, uint32_t cnt) {
    asm volatile("mbarrier.init.shared.b64 [%0], %1;" :: "r"(a), "r"(cnt) : "memory");
}
__device__ __forceinline__ void mbar_expect_tx(uint32_t a, uint32_t bytes) {
    asm volatile("mbarrier.arrive.expect_tx.shared.b64 _, [%0], %1;"
                 :: "r"(a), "r"(bytes) : "memory");
}
__device__ __forceinline__ void mbar_wait(uint32_t a, uint32_t parity) {
    asm volatile(
        "{\n\t.reg .pred P;\n\t"
        "WL_%=:\n\t"
        "mbarrier.try_wait.parity.acquire.cta.shared::cta.b64 P, [%0], %1, 0x989680;\n\t"
        "@P bra.uni WD_%=;\n\t"
        "bra.uni WL_%=;\n\t"
        "WD_%=:\n\t}"
        :: "r"(a), "r"(parity) : "memory");
}
__device__ __forceinline__ void bulk_g2s(uint32_t dst, const void* src, uint32_t bytes, uint32_t mbar) {
    asm volatile(
        "cp.async.bulk.shared::cta.global.mbarrier::complete_tx::bytes [%0], [%1], %2, [%3];"
        :: "r"(dst), "l"(src), "r"(bytes), "r"(mbar) : "memory");
}
__device__ __forceinline__ void ldsm_x4(uint32_t addr, uint32_t* r) {
    asm volatile("ldmatrix.sync.aligned.m8n8.x4.shared.b16 {%0,%1,%2,%3}, [%4];"
                 : "=r"(r[0]), "=r"(r[1]), "=r"(r[2]), "=r"(r[3]) : "r"(addr));
}
__device__ __forceinline__ void mma_f16(float* c, const uint32_t* a, const uint32_t* b) {
    asm volatile(
        "mma.sync.aligned.m16n8k16.row.col.f32.f16.f16.f32 "
        "{%0,%1,%2,%3}, {%4,%5,%6,%7}, {%8,%9}, {%0,%1,%2,%3};"
        : "+f"(c[0]), "+f"(c[1]), "+f"(c[2]), "+f"(c[3])
        : "r"(a[0]), "r"(a[1]), "r"(a[2]), "r"(a[3]), "r"(b[0]), "r"(b[1]));
}
__device__ __forceinline__ uint32_t sw128(uint32_t bo) { return bo ^ ((bo >> 3) & 0x70); }

// ------------------------------------------------------------------
// GEMM: C[M,N] = A[M,K] @ W[N,K]^T, packed fp16 operands, fp32 accum.
// BMx128 CTA tile, 4 warps (warp tile BM/2 x 64), k-chunk 64,
// 3-stage bulk-copy ring. 128 threads, 2 CTAs/SM.
// modes: 0 store f32 | 1 +res1 f32 | 2 bias+relu -> packed fp16 | 3 bias+res1+res2 f32
// ------------------------------------------------------------------
template<int BM>
__global__ __launch_bounds__(128, 2)
void tc_gemm(const __half* __restrict__ Apk, const __half* __restrict__ Bpk,
             float* __restrict__ C, __half* __restrict__ Oh,
             int ldc, int N, int K, int mode,
             const float* __restrict__ bias,
             const float* __restrict__ res1, int ldr1,
             const float* __restrict__ res2, int ldr2) {
    constexpr int MF = BM / 32;                   // m-frags (16 rows) per warp
    constexpr int ABYTES = BM * 128;
    constexpr int STB = ABYTES + 16384;           // stage bytes (A + B tile)
    extern __shared__ char smem[];
    const uint32_t sb = smem_u32(smem);           // 3 mbarriers at sb+0/8/16
    const uint32_t tiles = sb + 1024;
    const int tid = threadIdx.x;
    const int wid = tid >> 5, lid = tid & 31;
    const int bm = blockIdx.y * BM;
    const int bn = blockIdx.x * 128;
    const int wm = (wid & 1) * (BM / 2);
    const int wn = (wid >> 1) * 64;
    const int nch = K >> 6;
    const size_t aBase = (size_t)(bm >> 7) * nch * 8192 + (size_t)((bm >> 6) & 1) * 4096;
    const size_t bBase = (size_t)(bn >> 7) * nch * 8192;

    if (tid == 0) {
        mbar_init(sb + 0, 1); mbar_init(sb + 8, 1); mbar_init(sb + 16, 1);
        asm volatile("fence.proxy.async.shared::cta;" ::: "memory");
    }
    __syncthreads();

    float acc[MF][8][4];
#pragma unroll
    for (int mf = 0; mf < MF; ++mf)
#pragma unroll
        for (int nf = 0; nf < 8; ++nf)
#pragma unroll
            for (int v = 0; v < 4; ++v) acc[mf][nf][v] = 0.0f;

    const int mat = lid >> 3;
    const int lrow = lid & 7;
    const int rowA = wm + (mat & 1) * 8 + lrow;
    const int kqA = (mat >> 1);
    const int rowB = wn + (mat >> 1) * 8 + lrow;
    const int kqB = (mat & 1);

    if (tid == 0) {
#pragma unroll
        for (int c = 0; c < 2; ++c) {
            const uint32_t mb = sb + c * 8;
            const uint32_t dst = tiles + c * STB;
            mbar_expect_tx(mb, STB);
            bulk_g2s(dst, Apk + aBase + (size_t)c * 8192, ABYTES, mb);
            bulk_g2s(dst + ABYTES, Bpk + bBase + (size_t)c * 8192, 16384, mb);
        }
    }

    for (int c = 0; c < nch; ++c) {
        if (tid == 0 && c + 2 < nch) {
            const int s = (c + 2) % 3;
            const uint32_t mb = sb + s * 8;
            const uint32_t dst = tiles + s * STB;
            mbar_expect_tx(mb, STB);
            bulk_g2s(dst, Apk + aBase + (size_t)(c + 2) * 8192, ABYTES, mb);
            bulk_g2s(dst + ABYTES, Bpk + bBase + (size_t)(c + 2) * 8192, 16384, mb);
        }
        mbar_wait(sb + (c % 3) * 8, (uint32_t)((c / 3) & 1));

        const uint32_t base = tiles + (c % 3) * STB;
#pragma unroll
        for (int ks = 0; ks < 4; ++ks) {
            uint32_t ah[MF][4], bf[16];
#pragma unroll
            for (int mf = 0; mf < MF; ++mf) {
                const uint32_t bo = (uint32_t)(rowA + mf * 16) * 128 + ks * 32 + kqA * 16;
                ldsm_x4(base + sw128(bo), ah[mf]);
            }
#pragma unroll
            for (int p = 0; p < 4; ++p) {
                const uint32_t bo = (uint32_t)(rowB + p * 16) * 128 + ks * 32 + kqB * 16;
                ldsm_x4(base + ABYTES + sw128(bo), &bf[p * 4]);
            }
#pragma unroll
            for (int mf = 0; mf < MF; ++mf)
#pragma unroll
                for (int nf = 0; nf < 8; ++nf)
                    mma_f16(acc[mf][nf], ah[mf], &bf[nf * 2]);
        }
        __syncthreads();
    }

    const int erow0 = bm + wm + (lid >> 2);
    const int ecol0 = bn + wn + (lid & 3) * 2;
#pragma unroll
    for (int mf = 0; mf < MF; ++mf)
#pragma unroll
        for (int nf = 0; nf < 8; ++nf)
#pragma unroll
            for (int half = 0; half < 2; ++half) {
                const int row = erow0 + mf * 16 + half * 8;
                const int col = ecol0 + nf * 8;
                if (col >= N) continue;
                float v0 = acc[mf][nf][half * 2 + 0];
                float v1 = acc[mf][nf][half * 2 + 1];
                if (mode == 0) {
                    *(float2*)(C + (size_t)row * ldc + col) = make_float2(v0, v1);
                } else if (mode == 1) {
                    const float2 rr = *(const float2*)(res1 + (size_t)row * ldr1 + col);
                    *(float2*)(C + (size_t)row * ldc + col) = make_float2(v0 + rr.x, v1 + rr.y);
                } else if (mode == 2) {
                    const float2 bb = *(const float2*)(bias + col);
                    v0 = fmaxf(v0 + bb.x, 0.f);
                    v1 = fmaxf(v1 + bb.y, 0.f);
                    *(__half2*)(Oh + pk(row, col, ldc)) =
                        __half2(__float2half_rn(v0), __float2half_rn(v1));
                } else {
                    const float2 bb = *(const float2*)(bias + col);
                    const float2 r1 = *(const float2*)(res1 + (size_t)row * ldr1 + col);
                    const float2 r2 = *(const float2*)(res2 + (size_t)row * ldr2 + col);
                    *(float2*)(C + (size_t)row * ldc + col) =
                        make_float2(v0 + bb.x + r1.x + r2.x, v1 + bb.y + r1.y + r2.y);
                }
            }
}

// ------------------------------------------------------------------
// LayerNorm (D=1024): optional fp32 out + packed fp16 out
// ------------------------------------------------------------------
__global__ void ln_kernel(const float* __restrict__ x, const float* __restrict__ g,
                          const float* __restrict__ b, float* __restrict__ outf,
                          __half* __restrict__ oh) {
    __shared__ float rs[8], rq[8];
    const int tid = threadIdx.x;
    const size_t base = (size_t)blockIdx.x * DMODEL;
    float4 xv = *(const float4*)(x + base + tid * 4);
    float s = xv.x + xv.y + xv.z + xv.w;
    float q = xv.x * xv.x + xv.y * xv.y + xv.z * xv.z + xv.w * xv.w;
#pragma unroll
    for (int o = 16; o > 0; o >>= 1) {
        s += __shfl_xor_sync(0xffffffffu, s, o);
        q += __shfl_xor_sync(0xffffffffu, q, o);
    }
    if ((tid & 31) == 0) { rs[tid >> 5] = s; rq[tid >> 5] = q; }
    __syncthreads();
    s = rs[0] + rs[1] + rs[2] + rs[3] + rs[4] + rs[5] + rs[6] + rs[7];
    q = rq[0] + rq[1] + rq[2] + rq[3] + rq[4] + rq[5] + rq[6] + rq[7];
    const float mu = s * (1.0f / DMODEL);
    const float var = q * (1.0f / DMODEL) - mu * mu;
    const float rstd = rsqrtf(var + 1e-5f);
    float4 gv = *(const float4*)(g + tid * 4);
    float4 bv = *(const float4*)(b + tid * 4);
    float o0 = (xv.x - mu) * rstd * gv.x + bv.x;
    float o1 = (xv.y - mu) * rstd * gv.y + bv.y;
    float o2 = (xv.z - mu) * rstd * gv.z + bv.z;
    float o3 = (xv.w - mu) * rstd * gv.w + bv.w;
    if (outf) *(float4*)(outf + base + tid * 4) = make_float4(o0, o1, o2, o3);
    const int col = tid * 4;
    __half2* ph = (__half2*)(oh + pk(blockIdx.x, col, DMODEL));
    ph[0] = __half2(__float2half_rn(o0), __float2half_rn(o1));
    ph[1] = __half2(__float2half_rn(o2), __float2half_rn(o3));
}

// ------------------------------------------------------------------
// weight fp32 -> packed fp16 (4 elems/thread)
// ------------------------------------------------------------------
__global__ void cvt_h(const float4* __restrict__ src, __half* __restrict__ dst,
                      int n4, int kshift) {
    const int i = blockIdx.x * blockDim.x + threadIdx.x;
    if (i < n4) {
        const float4 v = src[i];
        const int e = i << 2;
        const int row = e >> kshift;
        const int col = e & ((1 << kshift) - 1);
        __half2* p = (__half2*)(dst + pk(row, col, 1 << kshift));
        p[0] = __half2(__float2half_rn(v.x), __float2half_rn(v.y));
        p[1] = __half2(__float2half_rn(v.z), __float2half_rn(v.w));
    }
}

// ------------------------------------------------------------------
// causal depthwise conv + SiLU -> xc fp32 + packed fp16
// ------------------------------------------------------------------
__global__ void conv_silu_kernel(const float* __restrict__ conv_w, const float* __restrict__ conv_b) {
    const int idx = blockIdx.x * blockDim.x + threadIdx.x;
    const int d = idx & (DI - 1);
    const int t = idx >> 11;
    float acc = conv_b[d];
#pragma unroll
    for (int k = 0; k < 4; ++k) {
        const int tt = t + k - 3;
        if (tt >= 0) acc = fmaf(g_xz[(size_t)tt * (2 * DI) + d], conv_w[d * 4 + k], acc);
    }
    const float v = acc / (1.0f + __expf(-acc));
    g_xc[idx] = v;
    g_xc_h[pk(t, d, DI)] = __float2half_rn(v);
}

// ------------------------------------------------------------------
// pack (B, C) from proj
// ------------------------------------------------------------------
__global__ void pack_bc_kernel() {
    const int i = blockIdx.x * blockDim.x + threadIdx.x;   // L*16
    const int t = i >> 4, s = i & 15;
    g_bc[i] = make_float2(g_proj[t * NPROJ + DTRANK + s],
                          g_proj[t * NPROJ + DTRANK + DSTATE + s]);
}

// ------------------------------------------------------------------
// delta GEMM (SIMT, K=64): dx = (softplus(dt @ Wdt^T + b), delta*xc)
// ------------------------------------------------------------------
__global__ __launch_bounds__(256, 2)
void delta_gemm(const float* __restrict__ P, const float* __restrict__ W,
                const float* __restrict__ bias) {
    __shared__ float As[8][128];
    __shared__ float Bs[8][128];
    const int tid = threadIdx.x;
    const int bm = blockIdx.y * 128;
    const int bn = blockIdx.x * 128;
    const int aRow = tid >> 1, aCol = (tid & 1) * 4;
    const int tx = tid & 15, ty = tid >> 4;
    float acc[8][8];
#pragma unroll
    for (int i = 0; i < 8; ++i)
#pragma unroll
        for (int j = 0; j < 8; ++j) acc[i][j] = 0.0f;
    for (int k0 = 0; k0 < 64; k0 += 8) {
        float4 av = *(const float4*)(P + (size_t)(bm + aRow) * NPROJ + k0 + aCol);
        float4 bv = *(const float4*)(W + (size_t)(bn + aRow) * 64 + k0 + aCol);
        __syncthreads();
        As[aCol + 0][aRow] = av.x; As[aCol + 1][aRow] = av.y;
        As[aCol + 2][aRow] = av.z; As[aCol + 3][aRow] = av.w;
        Bs[aCol + 0][aRow] = bv.x; Bs[aCol + 1][aRow] = bv.y;
        Bs[aCol + 2][aRow] = bv.z; Bs[aCol + 3][aRow] = bv.w;
        __syncthreads();
#pragma unroll
        for (int kk = 0; kk < 8; ++kk) {
            float rm[8], rn[8];
            *(float4*)&rm[0] = *(const float4*)&As[kk][ty * 8];
            *(float4*)&rm[4] = *(const float4*)&As[kk][ty * 8 + 4];
            *(float4*)&rn[0] = *(const float4*)&Bs[kk][tx * 8];
            *(float4*)&rn[4] = *(const float4*)&Bs[kk][tx * 8 + 4];
#pragma unroll
            for (int i = 0; i < 8; ++i)
#pragma unroll
                for (int j = 0; j < 8; ++j) acc[i][j] = fmaf(rm[i], rn[j], acc[i][j]);
        }
    }
#pragma unroll
    for (int i = 0; i < 8; ++i) {
        const int row = bm + ty * 8 + i;
#pragma unroll
        for (int j = 0; j < 8; ++j) {
            const int col = bn + tx * 8 + j;
            float v = acc[i][j] + bias[col];
            v = fmaxf(v, 0.0f) + log1pf(__expf(-fabsf(v)));
            const float xcv = g_xc[(size_t)row * DI + col];
            g_dx[(size_t)row * DI + col] = make_float2(v, v * xcv);
        }
    }
}

// ------------------------------------------------------------------
// selective scan: 16 lanes per channel, batch-8 timesteps,
// fully unrolled (register-resident buffers), deferred shfl reductions
// ------------------------------------------------------------------
__global__ void scan_kernel(const float* __restrict__ A_log) {
    const int s = threadIdx.x & 15;
    const int d = blockIdx.x * 16 + (threadIdx.x >> 4);
    const float a = -__expf(A_log[d * DSTATE + s]);
    float h = 0.0f;

    float2 cd[8], cb[8], nd[8], nb[8];
#pragma unroll
    for (int j = 0; j < 8; ++j) {
        cd[j] = g_dx[(size_t)j * DI + d];
        cb[j] = g_bc[j * DSTATE + s];
        nd[j] = make_float2(0.f, 0.f);
        nb[j] = make_float2(0.f, 0.f);
    }

    for (int t0 = 0; t0 < LSEQ; t0 += 8) {
        if (t0 + 8 < LSEQ) {
#pragma unroll
            for (int j = 0; j < 8; ++j) {
                nd[j] = g_dx[(size_t)(t0 + 8 + j) * DI + d];
                nb[j] = g_bc[(t0 + 8 + j) * DSTATE + s];
            }
        }
        float p[8];
#pragma unroll
        for (int j = 0; j < 8; ++j) {
            h = fmaf(h, __expf(a * cd[j].x), cd[j].y * cb[j].x);
            p[j] = h * cb[j].y;
        }
#pragma unroll
        for (int o = 1; o <= 8; o <<= 1)
#pragma unroll
            for (int j = 0; j < 8; ++j)
                p[j] += __shfl_xor_sync(0xffffffffu, p[j], o);
        if (s == 0) {
#pragma unroll
            for (int j = 0; j < 8; ++j)
                g_ys[(size_t)(t0 + j) * DI + d] = p[j];
        }
#pragma unroll
        for (int j = 0; j < 8; ++j) { cd[j] = nd[j]; cb[j] = nb[j]; }
    }
}

// ------------------------------------------------------------------
// y = (ys + xc*Dp) * silu(z) -> packed fp16
// ------------------------------------------------------------------
__global__ void ygate_kernel(const float* __restrict__ Dp) {
    const int idx = blockIdx.x * blockDim.x + threadIdx.x;
    const int d = idx & (DI - 1);
    const int t = idx >> 11;
    const float z = g_xz[(size_t)t * (2 * DI) + DI + d];
    const float sig = 1.0f / (1.0f + __expf(-z));
    const float v = fmaf(g_xc[idx], Dp[d], g_ys[idx]) * (z * sig);
    g_y_h[pk(t, d, DI)] = __float2half_rn(v);
}

// ------------------------------------------------------------------
// launch
// ------------------------------------------------------------------
#define SMEM_BIG   (1024 + 3 * (128 * 128 + 16384))   // 99328
#define SMEM_SMALL (1024 + 3 * (64 * 128 + 16384))    // 74752

extern "C" void kernel_launch(void* const* d_in, const int* in_sizes, int n_in,
                              void* d_out, int out_size) {
    const float* x         = (const float*)d_in[0];
    const float* ln1_g     = (const float*)d_in[1];
    const float* ln1_b     = (const float*)d_in[2];
    const float* ln2_g     = (const float*)d_in[3];
    const float* ln2_b     = (const float*)d_in[4];
    const float* in_proj_w = (const float*)d_in[5];
    const float* conv_w    = (const float*)d_in[6];
    const float* conv_b    = (const float*)d_in[7];
    const float* x_proj_w  = (const float*)d_in[8];
    const float* dt_proj_w = (const float*)d_in[9];
    const float* dt_proj_b = (const float*)d_in[10];
    const float* A_log     = (const float*)d_in[11];
    const float* D_param   = (const float*)d_in[12];
    const float* out_proj_w= (const float*)d_in[13];
    const float* ffn_w1    = (const float*)d_in[14];
    const float* ffn_b1    = (const float*)d_in[15];
    const float* ffn_w2    = (const float*)d_in[16];
    const float* ffn_b2    = (const float*)d_in[17];
    float* out = (float*)d_out;

    cudaFuncSetAttribute(tc_gemm<128>, cudaFuncAttributeMaxDynamicSharedMemorySize, SMEM_BIG);
    cudaFuncSetAttribute(tc_gemm<64>,  cudaFuncAttributeMaxDynamicSharedMemorySize, SMEM_SMALL);

#define SYM(p, s) void* p; cudaGetSymbolAddress(&p, s)
    SYM(p_xz, g_xz); SYM(p_xc, g_xc); SYM(p_proj, g_proj); SYM(p_h, g_h); SYM(p_n, g_n);
    SYM(p_hln_h, g_hln_h);
    SYM(p_xc_h, g_xc_h);
    SYM(p_y_h, g_y_h);
    SYM(p_n_h, g_n_h);
    SYM(p_f1_h, g_f1_h);
    SYM(p_win_h, g_win_h);
    SYM(p_wxp_h, g_wxp_h);
    SYM(p_wout_h, g_wout_h);
    SYM(p_wf1_h, g_wf1_h);
    SYM(p_wf2_h, g_wf2_h);
#undef SYM

    // weight conversions into packed-tile layout
    cvt_h<<<(2 * DI * DMODEL / 4 + 255) / 256, 256>>>((const float4*)in_proj_w, (__half*)p_win_h, 2 * DI * DMODEL / 4, 10);
    cvt_h<<<(NPROJ * DI / 4 + 255) / 256, 256>>>((const float4*)x_proj_w, (__half*)p_wxp_h, NPROJ * DI / 4, 11);
    cvt_h<<<(DMODEL * DI / 4 + 255) / 256, 256>>>((const float4*)out_proj_w, (__half*)p_wout_h, DMODEL * DI / 4, 11);
    cvt_h<<<(HIDF * DMODEL / 4 + 255) / 256, 256>>>((const float4*)ffn_w1, (__half*)p_wf1_h, HIDF * DMODEL / 4, 10);
    cvt_h<<<(DMODEL * HIDF / 4 + 255) / 256, 256>>>((const float4*)ffn_w2, (__half*)p_wf2_h, DMODEL * HIDF / 4, 12);

    // 1) LN1 -> hln (packed fp16)
    ln_kernel<<<LSEQ, 256>>>(x, ln1_g, ln1_b, nullptr, (__half*)p_hln_h);

    // 2) xz = hln @ in_proj_w^T   [2048, 4096]
    tc_gemm<128><<<dim3(32, 16), 128, SMEM_BIG>>>(
        (__half*)p_hln_h, (__half*)p_win_h,
        (float*)p_xz, nullptr, 2 * DI, 2 * DI, DMODEL, 0,
        nullptr, nullptr, 0, nullptr, 0);

    // 3) conv + silu -> xc (fp32 + packed fp16)
    conv_silu_kernel<<<(LSEQ * DI) / 256, 256>>>(conv_w, conv_b);

    // 4) proj = xc @ x_proj_w^T   [2048, 96]
    tc_gemm<64><<<dim3(1, 32), 128, SMEM_SMALL>>>(
        (__half*)p_xc_h, (__half*)p_wxp_h,
        (float*)p_proj, nullptr, NPROJ, NPROJ, DI, 0,
        nullptr, nullptr, 0, nullptr, 0);

    // 5) pack (B, C)
    pack_bc_kernel<<<(LSEQ * DSTATE) / 256, 256>>>();

    // 6) delta = softplus(dt @ dt_proj_w^T + b); dx = (delta, delta*xc)
    delta_gemm<<<dim3(DI / 128, LSEQ / 128), 256>>>((const float*)p_proj, dt_proj_w, dt_proj_b);

    // 7) selective scan (batched)
    scan_kernel<<<DI / 16, 256>>>(A_log);

    // 8) y gate -> y (packed fp16)
    ygate_kernel<<<(LSEQ * DI) / 256, 256>>>(D_param);

    // 9) h = y @ out_proj_w^T + x   [2048, 1024]
    tc_gemm<64><<<dim3(8, 32), 128, SMEM_SMALL>>>(
        (__half*)p_y_h, (__half*)p_wout_h,
        (float*)p_h, nullptr, DMODEL, DMODEL, DI, 1,
        nullptr, x, DMODEL, nullptr, 0);

    // 10) LN2 -> n (fp32 + packed fp16)
    ln_kernel<<<LSEQ, 256>>>((const float*)p_h, ln2_g, ln2_b, (float*)p_n, (__half*)p_n_h);

    // 11) f1 = relu(n @ ffn_w1^T + b1) -> packed fp16   [2048, 4096]
    tc_gemm<128><<<dim3(32, 16), 128, SMEM_BIG>>>(
        (__half*)p_n_h, (__half*)p_wf1_h,
        nullptr, (__half*)p_f1_h, HIDF, HIDF, DMODEL, 2,
        ffn_b1, nullptr, 0, nullptr, 0);

    // 12) out = f1 @ ffn_w2^T + b2 + n + h   [2048, 1024]
    tc_gemm<64><<<dim3(8, 32), 128, SMEM_SMALL>>>(
        (__half*)p_f1_h, (__half*)p_wf2_h,
        out, nullptr, DMODEL, DMODEL, HIDF, 3,
        ffn_b2, (const float*)p_n, DMODEL, (const float*)p_h, DMODEL);
}